// round 11
// baseline (speedup 1.0000x reference)
#include <cuda_runtime.h>
#include <cuda_bf16.h>
#include <math.h>

#define NNODES 100000
#define NEDGES 1600000
#define HDIM   128
#define NL     3
#define SCAN_B 512
#define NSCANB ((NNODES + SCAN_B - 1) / SCAN_B)   // 196

#define KSTRIDE 68                 // smem row stride in u32 (64 bf16-pairs + pad 4)
#define TILE_U32 (128 * KSTRIDE)   // 128-row bf16 tile in u32
#define HTILE_U32 (64 * KSTRIDE)   // 64-row bf16 tile in u32

// prepacked bf16 weight buffer offsets (u32 units)
#define OFF_WIH 0
#define OFF_WHH (OFF_WIH + 3 * 384 * 64)
#define OFF_GW1 (OFF_WHH + 3 * 384 * 64)
#define OFF_GW2 (OFF_GW1 + 3 * 128 * 64)
#define OFF_HW1 (OFF_GW2 + 3 * 128 * 64)
#define WB_TOTAL (OFF_HW1 + 3 * 128 * 64)

// ---------------- scratch (no allocations allowed) ----------------
__device__ unsigned g_xb  [(size_t)NNODES * 64];        // bf16 x
__device__ unsigned g_aggb[(size_t)NNODES * 64];        // bf16 agg
__device__ unsigned g_hb  [(size_t)NNODES * 64];        // bf16 h
__device__ unsigned g_wb  [WB_TOTAL];                   // prepacked weights
// CSR scratch
__device__ int   g_rowptr[NNODES + 1];
__device__ int   g_cursor[NNODES];
__device__ int   g_blocksum[NSCANB];
__device__ int   g_blockoff[NSCANB];
__device__ int2  g_csr_e[NEDGES];                       // {src, w_bits}

// ---------------- helpers ----------------
__device__ __forceinline__ unsigned pack_bf16(float a, float b) {
    __nv_bfloat162 t = __floats2bfloat162_rn(a, b);
    return *reinterpret_cast<unsigned*>(&t);
}

__device__ __forceinline__ void mma_bf16(float* d, const unsigned* a, const unsigned* b) {
    asm volatile(
        "mma.sync.aligned.m16n8k16.row.col.f32.bf16.bf16.f32 "
        "{%0,%1,%2,%3}, {%4,%5,%6,%7}, {%8,%9}, {%0,%1,%2,%3};\n"
        : "+f"(d[0]), "+f"(d[1]), "+f"(d[2]), "+f"(d[3])
        : "r"(a[0]), "r"(a[1]), "r"(a[2]), "r"(a[3]), "r"(b[0]), "r"(b[1]));
}

__device__ __forceinline__ void cpa16(unsigned* smem_dst, const unsigned* g, bool valid) {
    unsigned saddr = (unsigned)__cvta_generic_to_shared(smem_dst);
    int sz = valid ? 16 : 0;
    asm volatile("cp.async.cg.shared.global [%0], [%1], 16, %2;\n"
                 :: "r"(saddr), "l"(g), "r"(sz) : "memory");
}
__device__ __forceinline__ void cpa_commit() {
    asm volatile("cp.async.commit_group;\n" ::: "memory");
}
__device__ __forceinline__ void cpa_wait0() {
    asm volatile("cp.async.wait_group 0;\n" ::: "memory");
}
__device__ __forceinline__ void cpa_wait1() {
    asm volatile("cp.async.wait_group 1;\n" ::: "memory");
}

// 128-row tile async copy (weights)
__device__ __forceinline__ void cpa_tile(unsigned* dst, const unsigned* __restrict__ src,
                                         int tid) {
#pragma unroll
    for (int p = 0; p < 8; p++) {
        int F = p * 256 + tid;
        int row = F >> 4;
        int c4 = (F & 15) * 4;
        cpa16(dst + row * KSTRIDE + c4, src + (size_t)row * 64 + c4, true);
    }
}

// 64-row tile async copy (activations), OOB rows zero-filled
__device__ __forceinline__ void cpa_tile64(unsigned* dst, const unsigned* __restrict__ src,
                                           int row0, int Mrows, int tid) {
#pragma unroll
    for (int p = 0; p < 4; p++) {
        int F = p * 256 + tid;
        int row = F >> 4;
        int c4 = (F & 15) * 4;
        bool v = (row0 + row) < Mrows;
        cpa16(dst + row * KSTRIDE + c4, src + (size_t)(row0 + row) * 64 + c4, v);
    }
}

// acc += A64 @ W128^T for this warp (64-row A tile)
__device__ __forceinline__ void gemm64(const unsigned* __restrict__ As,
                                       const unsigned* __restrict__ Ws,
                                       float acc[8][4],
                                       int wm, int wn, int g, int t4) {
#pragma unroll
    for (int ks = 0; ks < 8; ks++) {
        int kb = ks * 8;
        int rb = wm * 16;
        unsigned af[4];
        af[0] = As[(rb + g) * KSTRIDE + kb + t4];
        af[1] = As[(rb + 8 + g) * KSTRIDE + kb + t4];
        af[2] = As[(rb + g) * KSTRIDE + kb + t4 + 4];
        af[3] = As[(rb + 8 + g) * KSTRIDE + kb + t4 + 4];
        unsigned bf[8][2];
#pragma unroll
        for (int j = 0; j < 8; j++) {
            int nb = wn * 64 + j * 8;
            bf[j][0] = Ws[(nb + g) * KSTRIDE + kb + t4];
            bf[j][1] = Ws[(nb + g) * KSTRIDE + kb + t4 + 4];
        }
#pragma unroll
        for (int j = 0; j < 8; j++)
            mma_bf16(acc[j], af, bf[j]);
    }
}

// 128-row variant (mlp1)
__device__ __forceinline__ void gemm128(const unsigned* __restrict__ As,
                                        const unsigned* __restrict__ Ws,
                                        float acc[2][8][4],
                                        int wm, int wn, int g, int t4) {
#pragma unroll
    for (int ks = 0; ks < 8; ks++) {
        int kb = ks * 8;
        unsigned af[2][4];
#pragma unroll
        for (int i = 0; i < 2; i++) {
            int rb = wm * 32 + i * 16;
            af[i][0] = As[(rb + g) * KSTRIDE + kb + t4];
            af[i][1] = As[(rb + 8 + g) * KSTRIDE + kb + t4];
            af[i][2] = As[(rb + g) * KSTRIDE + kb + t4 + 4];
            af[i][3] = As[(rb + 8 + g) * KSTRIDE + kb + t4 + 4];
        }
        unsigned bf[8][2];
#pragma unroll
        for (int j = 0; j < 8; j++) {
            int nb = wn * 64 + j * 8;
            bf[j][0] = Ws[(nb + g) * KSTRIDE + kb + t4];
            bf[j][1] = Ws[(nb + g) * KSTRIDE + kb + t4 + 4];
        }
#pragma unroll
        for (int i = 0; i < 2; i++)
#pragma unroll
            for (int j = 0; j < 8; j++)
                mma_bf16(acc[i][j], af[i], bf[j]);
    }
}

__device__ __forceinline__ void zero8(float acc[8][4]) {
#pragma unroll
    for (int j = 0; j < 8; j++)
#pragma unroll
        for (int r = 0; r < 4; r++) acc[j][r] = 0.f;
}

// load 128x128 f32 tile -> bf16 smem (mlp1 features / weights)
__device__ __forceinline__ void load_tile_g(unsigned* dst, const float* __restrict__ src,
                                            int row0, int M, int tid) {
#pragma unroll
    for (int p = 0; p < 16; p++) {
        int F = p * 256 + tid;
        int row = F >> 5, c = F & 31;
        float4 v = make_float4(0.f, 0.f, 0.f, 0.f);
        if (row0 + row < M) v = *reinterpret_cast<const float4*>(src + (size_t)(row0 + row) * HDIM + c * 4);
        dst[row * KSTRIDE + c * 2 + 0] = pack_bf16(v.x, v.y);
        dst[row * KSTRIDE + c * 2 + 1] = pack_bf16(v.z, v.w);
    }
}

__device__ __forceinline__ float sigm(float x) { return 1.f / (1.f + expf(-x)); }
__device__ __forceinline__ float bf_lo(unsigned p) { return __uint_as_float(p << 16); }
__device__ __forceinline__ float bf_hi(unsigned p) { return __uint_as_float(p & 0xffff0000u); }

// ---------------- weight prepack ----------------
__global__ void k_pack(const float4* __restrict__ src, uint2* __restrict__ dst, int n4) {
    int i = blockIdx.x * blockDim.x + threadIdx.x;
    if (i < n4) {
        float4 v = src[i];
        dst[i] = make_uint2(pack_bf16(v.x, v.y), pack_bf16(v.z, v.w));
    }
}

// ---------------- CSR build ----------------
__global__ void k_deg_zero(int* deg, int n) {
    int i = blockIdx.x * blockDim.x + threadIdx.x;
    if (i < n) deg[i] = 0;
}

__global__ void k_hist(const int* __restrict__ dst, int* __restrict__ deg, int E) {
    int i = blockIdx.x * blockDim.x + threadIdx.x;
    if (i < E) atomicAdd(&deg[dst[i]], 1);
}

__global__ __launch_bounds__(SCAN_B) void k_scan_local(const int* __restrict__ deg,
                                                       int* __restrict__ rowptr,
                                                       int* __restrict__ blocksum, int n) {
    __shared__ int s[SCAN_B];
    int tid = threadIdx.x;
    int i = blockIdx.x * SCAN_B + tid;
    int v = (i < n) ? deg[i] : 0;
    s[tid] = v;
    __syncthreads();
    for (int off = 1; off < SCAN_B; off <<= 1) {
        int t = (tid >= off) ? s[tid - off] : 0;
        __syncthreads();
        s[tid] += t;
        __syncthreads();
    }
    if (i < n) rowptr[i] = s[tid] - v;
    if (tid == SCAN_B - 1) blocksum[blockIdx.x] = s[tid];
}

// parallel exclusive scan of blocksum (nblk <= 256), one 256-thread block
__global__ __launch_bounds__(256) void k_scan_block2(const int* __restrict__ blocksum,
                                                     int* __restrict__ blockoff,
                                                     int* __restrict__ rowptr, int nblk, int n) {
    __shared__ int s[256];
    int tid = threadIdx.x;
    int v = (tid < nblk) ? blocksum[tid] : 0;
    s[tid] = v;
    __syncthreads();
    for (int off = 1; off < 256; off <<= 1) {
        int t = (tid >= off) ? s[tid - off] : 0;
        __syncthreads();
        s[tid] += t;
        __syncthreads();
    }
    if (tid < nblk) blockoff[tid] = s[tid] - v;
    if (tid == 255) rowptr[n] = s[255];
}

__global__ void k_scan_add(int* __restrict__ rowptr, int* __restrict__ cursor,
                           const int* __restrict__ blockoff, int n) {
    int i = blockIdx.x * blockDim.x + threadIdx.x;
    if (i < n) {
        int v = rowptr[i] + blockoff[i / SCAN_B];
        rowptr[i] = v;
        cursor[i] = v;
    }
}

__global__ void k_scatter(const int* __restrict__ dst, const int* __restrict__ src,
                          const float* __restrict__ ew, int* __restrict__ cursor,
                          int2* __restrict__ csr_e, int E) {
    int i = blockIdx.x * blockDim.x + threadIdx.x;
    if (i < E) {
        int pos = atomicAdd(&cursor[dst[i]], 1);
        csr_e[pos] = make_int2(src[i], __float_as_int(ew[i]));
    }
}

// ---------------- SpMM (CSR, warp per node, 4-edge unrolled bf16 gather) ----------------
__global__ __launch_bounds__(256) void k_spmm_b(
    const int* __restrict__ rowptr, const int2* __restrict__ csr_e,
    const unsigned* __restrict__ xb, unsigned* __restrict__ aggb, int n) {
    int row = (blockIdx.x * blockDim.x + threadIdx.x) >> 5;
    int lane = threadIdx.x & 31;
    if (row >= n) return;
    int e = rowptr[row];
    int end = rowptr[row + 1];
    const uint2* x2 = reinterpret_cast<const uint2*>(xb);
    float a0 = 0.f, a1 = 0.f, a2 = 0.f, a3 = 0.f;
    int e4 = e + ((end - e) & ~3);
    for (; e < e4; e += 4) {
        int2 E0 = csr_e[e];
        int2 E1 = csr_e[e + 1];
        int2 E2 = csr_e[e + 2];
        int2 E3 = csr_e[e + 3];
        uint2 v0 = x2[(size_t)E0.x * 32 + lane];
        uint2 v1 = x2[(size_t)E1.x * 32 + lane];
        uint2 v2 = x2[(size_t)E2.x * 32 + lane];
        uint2 v3 = x2[(size_t)E3.x * 32 + lane];
        float w0 = __int_as_float(E0.y), w1 = __int_as_float(E1.y);
        float w2 = __int_as_float(E2.y), w3 = __int_as_float(E3.y);
        a0 = fmaf(w0, bf_lo(v0.x), a0); a1 = fmaf(w0, bf_hi(v0.x), a1);
        a2 = fmaf(w0, bf_lo(v0.y), a2); a3 = fmaf(w0, bf_hi(v0.y), a3);
        a0 = fmaf(w1, bf_lo(v1.x), a0); a1 = fmaf(w1, bf_hi(v1.x), a1);
        a2 = fmaf(w1, bf_lo(v1.y), a2); a3 = fmaf(w1, bf_hi(v1.y), a3);
        a0 = fmaf(w2, bf_lo(v2.x), a0); a1 = fmaf(w2, bf_hi(v2.x), a1);
        a2 = fmaf(w2, bf_lo(v2.y), a2); a3 = fmaf(w2, bf_hi(v2.y), a3);
        a0 = fmaf(w3, bf_lo(v3.x), a0); a1 = fmaf(w3, bf_hi(v3.x), a1);
        a2 = fmaf(w3, bf_lo(v3.y), a2); a3 = fmaf(w3, bf_hi(v3.y), a3);
    }
    for (; e < end; e++) {
        int2 E0 = csr_e[e];
        float w0 = __int_as_float(E0.y);
        uint2 v0 = x2[(size_t)E0.x * 32 + lane];
        a0 = fmaf(w0, bf_lo(v0.x), a0); a1 = fmaf(w0, bf_hi(v0.x), a1);
        a2 = fmaf(w0, bf_lo(v0.y), a2); a3 = fmaf(w0, bf_hi(v0.y), a3);
    }
    *reinterpret_cast<uint2*>(aggb + (size_t)row * 64 + lane * 2) =
        make_uint2(pack_bf16(a0, a1), pack_bf16(a2, a3));
}

// ---------------- mlp1 GEMM: xb = bf16(relu(features @ w1^T + b1)) ----------------
__global__ __launch_bounds__(256) void k_gemm_mlp1(
    const float* __restrict__ A, const float* __restrict__ W,
    const float* __restrict__ bias, unsigned* __restrict__ Cb, int M)
{
    extern __shared__ unsigned smem_u[];
    unsigned* As = smem_u;
    unsigned* Ws = smem_u + TILE_U32;

    const int tid = threadIdx.x;
    const int wid = tid >> 5;
    const int lane = tid & 31;
    const int g = lane >> 2;
    const int t4 = lane & 3;
    const int wm = wid & 3;
    const int wn = wid >> 2;
    const int m0 = blockIdx.x * 128;

    load_tile_g(As, A, m0, M, tid);
#pragma unroll
    for (int p = 0; p < 16; p++) {
        int F = p * 256 + tid;
        int row = F >> 5, c = F & 31;
        float4 v = *reinterpret_cast<const float4*>(W + (size_t)row * HDIM + c * 4);
        Ws[row * KSTRIDE + c * 2 + 0] = pack_bf16(v.x, v.y);
        Ws[row * KSTRIDE + c * 2 + 1] = pack_bf16(v.z, v.w);
    }
    __syncthreads();

    float acc[2][8][4];
#pragma unroll
    for (int i = 0; i < 2; i++) zero8(acc[i]);
    gemm128(As, Ws, acc, wm, wn, g, t4);

#pragma unroll
    for (int i = 0; i < 2; i++) {
        int row_lo = m0 + wm * 32 + i * 16 + g;
        int row_hi = row_lo + 8;
#pragma unroll
        for (int j = 0; j < 8; j++) {
            int col = wn * 64 + j * 8 + 2 * t4;
            float b0 = bias[col];
            float b1 = bias[col + 1];
            if (row_lo < M)
                Cb[(size_t)row_lo * 64 + (col >> 1)] =
                    pack_bf16(fmaxf(acc[i][j][0] + b0, 0.f), fmaxf(acc[i][j][1] + b1, 0.f));
            if (row_hi < M)
                Cb[(size_t)row_hi * 64 + (col >> 1)] =
                    pack_bf16(fmaxf(acc[i][j][2] + b0, 0.f), fmaxf(acc[i][j][3] + b1, 0.f));
        }
    }
}
#define GEMM_SMEM (2 * TILE_U32 * 4)

// ---------------- fused GRU (64-row tiles, 2 CTA/SM) ----------------
__global__ __launch_bounds__(256, 2) void k_gru_fused(
    const unsigned* __restrict__ aggb, const unsigned* __restrict__ xb,
    const unsigned* __restrict__ wihb, const unsigned* __restrict__ whhb,
    const float* __restrict__ bih, const float* __restrict__ bhh,
    unsigned* __restrict__ hb, int M)
{
    extern __shared__ unsigned sm[];
    unsigned* Aagg = sm;
    unsigned* Ax   = sm + HTILE_U32;
    unsigned* Wb0  = sm + 2 * HTILE_U32;
    unsigned* Wb1  = Wb0 + TILE_U32;

    const int tid = threadIdx.x;
    const int wid = tid >> 5;
    const int lane = tid & 31;
    const int g = lane >> 2;
    const int t4 = lane & 3;
    const int wm = wid & 3;
    const int wn = wid >> 2;
    const int m0 = blockIdx.x * 64;

    // chunk order: c0=whh2, c1=wih0, c2=whh0, c3=wih2, c4=wih1, c5=whh1
    const unsigned* c0 = whhb + 256 * 64;
    const unsigned* c1 = wihb;
    const unsigned* c2 = whhb;
    const unsigned* c3 = wihb + 256 * 64;
    const unsigned* c4 = wihb + 128 * 64;
    const unsigned* c5 = whhb + 128 * 64;

    cpa_tile64(Aagg, aggb, m0, M, tid);
    cpa_tile64(Ax,   xb,   m0, M, tid);
    cpa_tile(Wb0, c0, tid);
    cpa_commit();                      // G0
    cpa_tile(Wb1, c1, tid);
    cpa_commit();                      // G1

    float accA[8][4], accB[8][4];
    zero8(accA); zero8(accB);

    cpa_wait1(); __syncthreads();
    gemm64(Ax, Wb0, accA, wm, wn, g, t4);          // accA = whh2 @ x
    __syncthreads();
    cpa_tile(Wb0, c2, tid); cpa_commit();          // G2

    cpa_wait1(); __syncthreads();
    gemm64(Aagg, Wb1, accB, wm, wn, g, t4);        // accB = wih0 @ agg
    __syncthreads();
    cpa_tile(Wb1, c3, tid); cpa_commit();          // G3

    cpa_wait1(); __syncthreads();
    gemm64(Ax, Wb0, accB, wm, wn, g, t4);          // accB += whh0 @ x  -> r
#pragma unroll
    for (int j = 0; j < 8; j++)
#pragma unroll
        for (int r = 0; r < 4; r++) {
            int col = wn * 64 + j * 8 + 2 * t4 + (r & 1);
            float rv = sigm(accB[j][r] + bih[col] + bhh[col]);
            accA[j][r] = rv * (accA[j][r] + bhh[256 + col]);   // fold r into n path
        }
    __syncthreads();
    cpa_tile(Wb0, c4, tid); cpa_commit();          // G4

    cpa_wait1(); __syncthreads();
    gemm64(Aagg, Wb1, accA, wm, wn, g, t4);        // accA += wih2 @ agg  (n preact)
    __syncthreads();
    cpa_tile(Wb1, c5, tid); cpa_commit();          // G5

    zero8(accB);
    cpa_wait1(); __syncthreads();
    gemm64(Aagg, Wb0, accB, wm, wn, g, t4);        // accB = wih1 @ agg
    cpa_wait0(); __syncthreads();
    gemm64(Ax, Wb1, accB, wm, wn, g, t4);          // accB += whh1 @ x -> z

    // h = (1-z)*tanh(accA + bih2) + z*x   (x from bf16 smem tile)
    int rl_lo = wm * 16 + g;
    int rl_hi = rl_lo + 8;
    int row_lo = m0 + rl_lo;
    int row_hi = m0 + rl_hi;
#pragma unroll
    for (int j = 0; j < 8; j++) {
        int col = wn * 64 + j * 8 + 2 * t4;
        if (row_lo < M) {
            unsigned xp = Ax[rl_lo * KSTRIDE + (col >> 1)];
            float z0 = sigm(accB[j][0] + bih[128 + col] + bhh[128 + col]);
            float z1 = sigm(accB[j][1] + bih[128 + col + 1] + bhh[128 + col + 1]);
            float n0 = tanhf(accA[j][0] + bih[256 + col]);
            float n1 = tanhf(accA[j][1] + bih[256 + col + 1]);
            hb[(size_t)row_lo * 64 + (col >> 1)] =
                pack_bf16((1.f - z0) * n0 + z0 * bf_lo(xp), (1.f - z1) * n1 + z1 * bf_hi(xp));
        }
        if (row_hi < M) {
            unsigned xp = Ax[rl_hi * KSTRIDE + (col >> 1)];
            float z2 = sigm(accB[j][2] + bih[128 + col] + bhh[128 + col]);
            float z3 = sigm(accB[j][3] + bih[128 + col + 1] + bhh[128 + col + 1]);
            float n2 = tanhf(accA[j][2] + bih[256 + col]);
            float n3 = tanhf(accA[j][3] + bih[256 + col + 1]);
            hb[(size_t)row_hi * 64 + (col >> 1)] =
                pack_bf16((1.f - z2) * n2 + z2 * bf_lo(xp), (1.f - z3) * n3 + z3 * bf_hi(xp));
        }
    }
}
#define GRU_SMEM ((2 * HTILE_U32 + 2 * TILE_U32) * 4)

// ---------------- fused GIN MLP + norm + head + softmax (64-row tiles) ----------------
template <int C>
__global__ __launch_bounds__(256, 2) void k_gin_head(
    const unsigned* __restrict__ hbt,
    const unsigned* __restrict__ g1b, const float* __restrict__ b1v,
    const unsigned* __restrict__ g2b, const float* __restrict__ b2v,
    const unsigned* __restrict__ hw1b, const float* __restrict__ hb1,
    const float* __restrict__ w2, const float* __restrict__ bh2,
    unsigned* __restrict__ xbout,
    float* __restrict__ olog, float* __restrict__ osoft,
    int M)
{
    extern __shared__ unsigned sm[];
    unsigned* Ah   = sm;                          // h tile / later x tile
    unsigned* At1  = sm + HTILE_U32;              // t1 / t2 / logits (aliased)
    unsigned* Wb0  = sm + 2 * HTILE_U32;          // g1 -> hw1
    unsigned* Wb1  = Wb0 + TILE_U32;              // g2
    unsigned* W2s  = Wb1 + TILE_U32;              // head w2 (24 rows)
    float* rowsum  = reinterpret_cast<float*>(W2s + 24 * KSTRIDE);  // [64]

    const int tid = threadIdx.x;
    const int wid = tid >> 5;
    const int lane = tid & 31;
    const int g = lane >> 2;
    const int t4 = lane & 3;
    const int wm = wid & 3;
    const int wn = wid >> 2;
    const int m0 = blockIdx.x * 64;

    if (tid < 64) rowsum[tid] = 0.f;
    cpa_tile64(Ah, hbt, m0, M, tid);
    cpa_tile(Wb0, g1b, tid);
    cpa_commit();                      // G0
    cpa_tile(Wb1, g2b, tid);
    cpa_commit();                      // G1

    float acc[8][4];

    // ---- t1 = relu(h @ g1^T + b1) ----
    zero8(acc);
    cpa_wait1(); __syncthreads();
    gemm64(Ah, Wb0, acc, wm, wn, g, t4);
    {
        int rl = wm * 16 + g;
#pragma unroll
        for (int j = 0; j < 8; j++) {
            int col = wn * 64 + j * 8 + 2 * t4;
            At1[rl * KSTRIDE + (col >> 1)] =
                pack_bf16(fmaxf(acc[j][0] + b1v[col], 0.f), fmaxf(acc[j][1] + b1v[col + 1], 0.f));
            At1[(rl + 8) * KSTRIDE + (col >> 1)] =
                pack_bf16(fmaxf(acc[j][2] + b1v[col], 0.f), fmaxf(acc[j][3] + b1v[col + 1], 0.f));
        }
    }
    __syncthreads();
    cpa_tile(Wb0, hw1b, tid); cpa_commit();        // G2

    // ---- x = relu(t1 @ g2^T + b2), rowsum ----
    zero8(acc);
    cpa_wait1(); __syncthreads();
    gemm64(At1, Wb1, acc, wm, wn, g, t4);
    {
        float s_lo = 0.f, s_hi = 0.f;
#pragma unroll
        for (int j = 0; j < 8; j++) {
            int col = wn * 64 + j * 8 + 2 * t4;
            acc[j][0] = fmaxf(acc[j][0] + b2v[col], 0.f);
            acc[j][1] = fmaxf(acc[j][1] + b2v[col + 1], 0.f);
            acc[j][2] = fmaxf(acc[j][2] + b2v[col], 0.f);
            acc[j][3] = fmaxf(acc[j][3] + b2v[col + 1], 0.f);
            s_lo += acc[j][0] * acc[j][0] + acc[j][1] * acc[j][1];
            s_hi += acc[j][2] * acc[j][2] + acc[j][3] * acc[j][3];
        }
        atomicAdd(&rowsum[wm * 16 + g], s_lo);
        atomicAdd(&rowsum[wm * 16 + 8 + g], s_hi);
    }
    __syncthreads();

    // ---- normalize, write bf16 x, repack to Ah; load W2s ----
    {
        int rl = wm * 16 + g;
        float inv_lo = rsqrtf(1.f + rowsum[rl]);
        float inv_hi = rsqrtf(1.f + rowsum[rl + 8]);
        int gm_lo = m0 + rl;
        int gm_hi = gm_lo + 8;
#pragma unroll
        for (int j = 0; j < 8; j++) {
            int col = wn * 64 + j * 8 + 2 * t4;
            unsigned p_lo = pack_bf16(acc[j][0] * inv_lo, acc[j][1] * inv_lo);
            unsigned p_hi = pack_bf16(acc[j][2] * inv_hi, acc[j][3] * inv_hi);
            Ah[rl * KSTRIDE + (col >> 1)] = p_lo;
            Ah[(rl + 8) * KSTRIDE + (col >> 1)] = p_hi;
            if (gm_lo < M) xbout[(size_t)gm_lo * 64 + (col >> 1)] = p_lo;
            if (gm_hi < M) xbout[(size_t)gm_hi * 64 + (col >> 1)] = p_hi;
        }
    }
    for (int idx = tid; idx < 24 * 32; idx += 256) {
        int row = idx >> 5, c = idx & 31;
        float4 v = make_float4(0.f, 0.f, 0.f, 0.f);
        if (row < C) v = *reinterpret_cast<const float4*>(w2 + (size_t)row * HDIM + c * 4);
        W2s[row * KSTRIDE + c * 2 + 0] = pack_bf16(v.x, v.y);
        W2s[row * KSTRIDE + c * 2 + 1] = pack_bf16(v.z, v.w);
    }
    __syncthreads();

    // ---- t2 = relu(x @ hw1^T + hb1) -> At1 ----
    zero8(acc);
    cpa_wait0(); __syncthreads();
    gemm64(Ah, Wb0, acc, wm, wn, g, t4);
    {
        int rl = wm * 16 + g;
#pragma unroll
        for (int j = 0; j < 8; j++) {
            int col = wn * 64 + j * 8 + 2 * t4;
            At1[rl * KSTRIDE + (col >> 1)] =
                pack_bf16(fmaxf(acc[j][0] + hb1[col], 0.f), fmaxf(acc[j][1] + hb1[col + 1], 0.f));
            At1[(rl + 8) * KSTRIDE + (col >> 1)] =
                pack_bf16(fmaxf(acc[j][2] + hb1[col], 0.f), fmaxf(acc[j][3] + hb1[col + 1], 0.f));
        }
    }
    __syncthreads();

    // ---- head logits: t2 @ w2^T (warps with wn==0 cover all 64 rows) ----
    float hacc[3][4];
#pragma unroll
    for (int j = 0; j < 3; j++)
#pragma unroll
        for (int r = 0; r < 4; r++) hacc[j][r] = 0.f;
    if (wn == 0) {
#pragma unroll
        for (int ks = 0; ks < 8; ks++) {
            int kb = ks * 8;
            int rb = wm * 16;
            unsigned af[4];
            af[0] = At1[(rb + g) * KSTRIDE + kb + t4];
            af[1] = At1[(rb + 8 + g) * KSTRIDE + kb + t4];
            af[2] = At1[(rb + g) * KSTRIDE + kb + t4 + 4];
            af[3] = At1[(rb + 8 + g) * KSTRIDE + kb + t4 + 4];
            unsigned bfr[3][2];
#pragma unroll
            for (int j = 0; j < 3; j++) {
                int nb = j * 8;
                bfr[j][0] = W2s[(nb + g) * KSTRIDE + kb + t4];
                bfr[j][1] = W2s[(nb + g) * KSTRIDE + kb + t4 + 4];
            }
#pragma unroll
            for (int j = 0; j < 3; j++)
                mma_bf16(hacc[j], af, bfr[j]);
        }
    }
    __syncthreads();                 // all reads of At1 complete
    float* logitp = reinterpret_cast<float*>(At1);   // [64][28]
    if (wn == 0) {
        int rl = wm * 16 + g;
#pragma unroll
        for (int j = 0; j < 3; j++) {
            int col = j * 8 + 2 * t4;
            logitp[rl * 28 + col] = hacc[j][0];
            logitp[rl * 28 + col + 1] = hacc[j][1];
            logitp[(rl + 8) * 28 + col] = hacc[j][2];
            logitp[(rl + 8) * 28 + col + 1] = hacc[j][3];
        }
    }
    __syncthreads();

    // ---- softmax / log_softmax (8 nodes per warp) ----
#pragma unroll
    for (int k = 0; k < 8; k++) {
        int nl = wid * 8 + k;
        int gm = m0 + nl;
        float myval = (lane < C) ? (logitp[nl * 28 + lane] + bh2[lane]) : 0.f;
        float mx = (lane < C) ? myval : -INFINITY;
#pragma unroll
        for (int o = 16; o; o >>= 1) mx = fmaxf(mx, __shfl_xor_sync(0xffffffffu, mx, o));
        float e = (lane < C) ? expf(myval - mx) : 0.f;
        float s = e;
#pragma unroll
        for (int o = 16; o; o >>= 1) s += __shfl_xor_sync(0xffffffffu, s, o);
        if (gm < M && lane < C) {
            olog [(size_t)gm * C + lane] = myval - mx - logf(s);
            osoft[(size_t)gm * C + lane] = e / s;
        }
    }
}
#define GIN_SMEM ((2 * HTILE_U32 + 2 * TILE_U32 + 24 * KSTRIDE + 64) * 4)

// ---------------- launch ----------------
extern "C" void kernel_launch(void* const* d_in, const int* in_sizes, int n_in,
                              void* d_out, int out_size) {
    const float* features = (const float*)d_in[0];
    const int*   eidx     = (const int*)  d_in[1];
    const float* ew       = (const float*)d_in[2];
    const float* w1       = (const float*)d_in[3];
    const float* b1       = (const float*)d_in[4];
    const float* gin_w1   = (const float*)d_in[5];
    const float* gin_b1   = (const float*)d_in[6];
    const float* gin_w2   = (const float*)d_in[7];
    const float* gin_b2   = (const float*)d_in[8];
    const float* gru_wih  = (const float*)d_in[9];
    const float* gru_whh  = (const float*)d_in[10];
    const float* gru_bih  = (const float*)d_in[11];
    const float* gru_bhh  = (const float*)d_in[12];
    const float* head_w1  = (const float*)d_in[13];
    const float* head_b1  = (const float*)d_in[14];
    const float* hw2_0    = (const float*)d_in[15];
    const float* hb2_0    = (const float*)d_in[16];
    const float* hw2_1    = (const float*)d_in[17];
    const float* hb2_1    = (const float*)d_in[18];
    const float* hw2_2    = (const float*)d_in[19];
    const float* hb2_2    = (const float*)d_in[20];

    float* out = (float*)d_out;

    unsigned *p_xb, *p_aggb, *p_hb, *p_wb;
    int2 *p_csr_e;
    int *p_rowptr, *p_cursor, *p_bsum, *p_boff;
    cudaGetSymbolAddress((void**)&p_xb,     g_xb);
    cudaGetSymbolAddress((void**)&p_aggb,   g_aggb);
    cudaGetSymbolAddress((void**)&p_hb,     g_hb);
    cudaGetSymbolAddress((void**)&p_wb,     g_wb);
    cudaGetSymbolAddress((void**)&p_rowptr, g_rowptr);
    cudaGetSymbolAddress((void**)&p_cursor, g_cursor);
    cudaGetSymbolAddress((void**)&p_bsum,   g_blocksum);
    cudaGetSymbolAddress((void**)&p_boff,   g_blockoff);
    cudaGetSymbolAddress((void**)&p_csr_e,  g_csr_e);

    cudaFuncSetAttribute(k_gemm_mlp1,    cudaFuncAttributeMaxDynamicSharedMemorySize, GEMM_SMEM);
    cudaFuncSetAttribute(k_gru_fused,    cudaFuncAttributeMaxDynamicSharedMemorySize, GRU_SMEM);
    cudaFuncSetAttribute(k_gin_head<2>,  cudaFuncAttributeMaxDynamicSharedMemorySize, GIN_SMEM);
    cudaFuncSetAttribute(k_gin_head<6>,  cudaFuncAttributeMaxDynamicSharedMemorySize, GIN_SMEM);
    cudaFuncSetAttribute(k_gin_head<21>, cudaFuncAttributeMaxDynamicSharedMemorySize, GIN_SMEM);

    const int M = NNODES;
    const int E = NEDGES;
    const int tile_gx   = (M + 127) / 128;   // 782
    const int tile64_gx = (M + 63) / 64;     // 1563
    const int warp_blocks = (M * 32 + 255) / 256;
    const int edge_blocks = (E + 255) / 256;
    const int node_blocks = (M + 255) / 256;

    const int* e_dst = eidx;
    const int* e_src = eidx + E;

    const size_t o_log0 = 0;
    const size_t o_log1 = (size_t)M * 2;
    const size_t o_log2 = (size_t)M * 8;
    const size_t o_soft = (size_t)M * 29;

    // ---- prepack weights to bf16 ----
    {
        int n4;
        n4 = 3 * 384 * HDIM / 4;
        k_pack<<<(n4 + 255) / 256, 256>>>((const float4*)gru_wih, (uint2*)(p_wb + OFF_WIH), n4);
        k_pack<<<(n4 + 255) / 256, 256>>>((const float4*)gru_whh, (uint2*)(p_wb + OFF_WHH), n4);
        n4 = 3 * HDIM * HDIM / 4;
        k_pack<<<(n4 + 255) / 256, 256>>>((const float4*)gin_w1,  (uint2*)(p_wb + OFF_GW1), n4);
        k_pack<<<(n4 + 255) / 256, 256>>>((const float4*)gin_w2,  (uint2*)(p_wb + OFF_GW2), n4);
        k_pack<<<(n4 + 255) / 256, 256>>>((const float4*)head_w1, (uint2*)(p_wb + OFF_HW1), n4);
    }

    // ---- build CSR ----
    k_deg_zero<<<node_blocks, 256>>>(p_cursor, M);
    k_hist<<<edge_blocks, 256>>>(e_dst, p_cursor, E);
    k_scan_local<<<NSCANB, SCAN_B>>>(p_cursor, p_rowptr, p_bsum, M);
    k_scan_block2<<<1, 256>>>(p_bsum, p_boff, p_rowptr, NSCANB, M);
    k_scan_add<<<node_blocks, 256>>>(p_rowptr, p_cursor, p_boff, M);
    k_scatter<<<edge_blocks, 256>>>(e_dst, e_src, ew, p_cursor, p_csr_e, E);

    // x = relu(features @ w1^T + b1)  (bf16)
    k_gemm_mlp1<<<tile_gx, 256, GEMM_SMEM>>>(features, w1, b1, p_xb, M);

    for (int i = 0; i < NL; i++) {
        k_spmm_b<<<warp_blocks, 256>>>(p_rowptr, p_csr_e, p_xb, p_aggb, M);

        k_gru_fused<<<tile64_gx, 256, GRU_SMEM>>>(
            p_aggb, p_xb,
            p_wb + OFF_WIH + (size_t)i * 384 * 64,
            p_wb + OFF_WHH + (size_t)i * 384 * 64,
            gru_bih + (size_t)i * 384, gru_bhh + (size_t)i * 384,
            p_hb, M);

        const unsigned* g1b  = p_wb + OFF_GW1 + (size_t)i * 128 * 64;
        const unsigned* g2b  = p_wb + OFF_GW2 + (size_t)i * 128 * 64;
        const unsigned* hw1b = p_wb + OFF_HW1 + (size_t)i * 128 * 64;
        if (i == 0)
            k_gin_head<2><<<tile64_gx, 256, GIN_SMEM>>>(
                p_hb, g1b, gin_b1, g2b, gin_b2,
                hw1b, head_b1, hw2_0, hb2_0,
                p_xb, out + o_log0, out + o_soft, M);
        else if (i == 1)
            k_gin_head<6><<<tile64_gx, 256, GIN_SMEM>>>(
                p_hb, g1b, gin_b1 + HDIM, g2b, gin_b2 + HDIM,
                hw1b, head_b1 + HDIM, hw2_1, hb2_1,
                p_xb, out + o_log1, out + o_soft + (size_t)M * 2, M);
        else
            k_gin_head<21><<<tile64_gx, 256, GIN_SMEM>>>(
                p_hb, g1b, gin_b1 + 2 * HDIM, g2b, gin_b2 + 2 * HDIM,
                hw1b, head_b1 + 2 * HDIM, hw2_2, hb2_2,
                p_xb, out + o_log2, out + o_soft + (size_t)M * 8, M);
    }
}

// round 12
// speedup vs baseline: 1.5641x; 1.5641x over previous
#include <cuda_runtime.h>
#include <cuda_bf16.h>
#include <math.h>

#define NNODES 100000
#define NEDGES 1600000
#define HDIM   128
#define NL     3
#define SCAN_B 512
#define NSCANB ((NNODES + SCAN_B - 1) / SCAN_B)   // 196

#define KSTRIDE 68                 // smem row stride in u32 (64 bf16-pairs + pad 4)
#define TILE_U32 (128 * KSTRIDE)   // 128-row bf16 tile in u32
#define HTILE_U32 (64 * KSTRIDE)   // 64-row bf16 tile in u32

// prepacked bf16 weight buffer offsets (u32 units)
#define OFF_WIH 0
#define OFF_WHH (OFF_WIH + 3 * 384 * 64)
#define OFF_GW1 (OFF_WHH + 3 * 384 * 64)
#define OFF_GW2 (OFF_GW1 + 3 * 128 * 64)
#define OFF_HW1 (OFF_GW2 + 3 * 128 * 64)
#define WB_TOTAL (OFF_HW1 + 3 * 128 * 64)

// ---------------- scratch (no allocations allowed) ----------------
__device__ unsigned g_xb  [(size_t)NNODES * 64];        // bf16 x
__device__ unsigned g_aggb[(size_t)NNODES * 64];        // bf16 agg
__device__ unsigned g_wb  [WB_TOTAL];                   // prepacked weights
// CSR scratch
__device__ int   g_rowptr[NNODES + 1];
__device__ int   g_cursor[NNODES];
__device__ int   g_blocksum[NSCANB];
__device__ int   g_blockoff[NSCANB];
__device__ int2  g_csr_e[NEDGES];                       // {src, w_bits}

// ---------------- helpers ----------------
__device__ __forceinline__ unsigned pack_bf16(float a, float b) {
    __nv_bfloat162 t = __floats2bfloat162_rn(a, b);
    return *reinterpret_cast<unsigned*>(&t);
}

__device__ __forceinline__ void mma_bf16(float* d, const unsigned* a, const unsigned* b) {
    asm volatile(
        "mma.sync.aligned.m16n8k16.row.col.f32.bf16.bf16.f32 "
        "{%0,%1,%2,%3}, {%4,%5,%6,%7}, {%8,%9}, {%0,%1,%2,%3};\n"
        : "+f"(d[0]), "+f"(d[1]), "+f"(d[2]), "+f"(d[3])
        : "r"(a[0]), "r"(a[1]), "r"(a[2]), "r"(a[3]), "r"(b[0]), "r"(b[1]));
}

__device__ __forceinline__ void cpa16(unsigned* smem_dst, const unsigned* g, bool valid) {
    unsigned saddr = (unsigned)__cvta_generic_to_shared(smem_dst);
    int sz = valid ? 16 : 0;
    asm volatile("cp.async.cg.shared.global [%0], [%1], 16, %2;\n"
                 :: "r"(saddr), "l"(g), "r"(sz) : "memory");
}
__device__ __forceinline__ void cpa_commit() {
    asm volatile("cp.async.commit_group;\n" ::: "memory");
}
__device__ __forceinline__ void cpa_wait0() {
    asm volatile("cp.async.wait_group 0;\n" ::: "memory");
}
__device__ __forceinline__ void cpa_wait1() {
    asm volatile("cp.async.wait_group 1;\n" ::: "memory");
}

// 128-row tile async copy (weights)
__device__ __forceinline__ void cpa_tile(unsigned* dst, const unsigned* __restrict__ src,
                                         int tid) {
#pragma unroll
    for (int p = 0; p < 8; p++) {
        int F = p * 256 + tid;
        int row = F >> 4;
        int c4 = (F & 15) * 4;
        cpa16(dst + row * KSTRIDE + c4, src + (size_t)row * 64 + c4, true);
    }
}

// 64-row tile async copy (activations), OOB rows zero-filled
__device__ __forceinline__ void cpa_tile64(unsigned* dst, const unsigned* __restrict__ src,
                                           int row0, int Mrows, int tid) {
#pragma unroll
    for (int p = 0; p < 4; p++) {
        int F = p * 256 + tid;
        int row = F >> 4;
        int c4 = (F & 15) * 4;
        bool v = (row0 + row) < Mrows;
        cpa16(dst + row * KSTRIDE + c4, src + (size_t)(row0 + row) * 64 + c4, v);
    }
}

// acc += A64 @ W128^T for this warp (64-row A tile)
__device__ __forceinline__ void gemm64(const unsigned* __restrict__ As,
                                       const unsigned* __restrict__ Ws,
                                       float acc[8][4],
                                       int wm, int wn, int g, int t4) {
#pragma unroll
    for (int ks = 0; ks < 8; ks++) {
        int kb = ks * 8;
        int rb = wm * 16;
        unsigned af[4];
        af[0] = As[(rb + g) * KSTRIDE + kb + t4];
        af[1] = As[(rb + 8 + g) * KSTRIDE + kb + t4];
        af[2] = As[(rb + g) * KSTRIDE + kb + t4 + 4];
        af[3] = As[(rb + 8 + g) * KSTRIDE + kb + t4 + 4];
        unsigned bf[8][2];
#pragma unroll
        for (int j = 0; j < 8; j++) {
            int nb = wn * 64 + j * 8;
            bf[j][0] = Ws[(nb + g) * KSTRIDE + kb + t4];
            bf[j][1] = Ws[(nb + g) * KSTRIDE + kb + t4 + 4];
        }
#pragma unroll
        for (int j = 0; j < 8; j++)
            mma_bf16(acc[j], af, bf[j]);
    }
}

// 128-row variant (mlp1)
__device__ __forceinline__ void gemm128(const unsigned* __restrict__ As,
                                        const unsigned* __restrict__ Ws,
                                        float acc[2][8][4],
                                        int wm, int wn, int g, int t4) {
#pragma unroll
    for (int ks = 0; ks < 8; ks++) {
        int kb = ks * 8;
        unsigned af[2][4];
#pragma unroll
        for (int i = 0; i < 2; i++) {
            int rb = wm * 32 + i * 16;
            af[i][0] = As[(rb + g) * KSTRIDE + kb + t4];
            af[i][1] = As[(rb + 8 + g) * KSTRIDE + kb + t4];
            af[i][2] = As[(rb + g) * KSTRIDE + kb + t4 + 4];
            af[i][3] = As[(rb + 8 + g) * KSTRIDE + kb + t4 + 4];
        }
        unsigned bf[8][2];
#pragma unroll
        for (int j = 0; j < 8; j++) {
            int nb = wn * 64 + j * 8;
            bf[j][0] = Ws[(nb + g) * KSTRIDE + kb + t4];
            bf[j][1] = Ws[(nb + g) * KSTRIDE + kb + t4 + 4];
        }
#pragma unroll
        for (int i = 0; i < 2; i++)
#pragma unroll
            for (int j = 0; j < 8; j++)
                mma_bf16(acc[i][j], af[i], bf[j]);
    }
}

__device__ __forceinline__ void zero8(float acc[8][4]) {
#pragma unroll
    for (int j = 0; j < 8; j++)
#pragma unroll
        for (int r = 0; r < 4; r++) acc[j][r] = 0.f;
}

// load 128x128 f32 tile -> bf16 smem (mlp1 features / weights)
__device__ __forceinline__ void load_tile_g(unsigned* dst, const float* __restrict__ src,
                                            int row0, int M, int tid) {
#pragma unroll
    for (int p = 0; p < 16; p++) {
        int F = p * 256 + tid;
        int row = F >> 5, c = F & 31;
        float4 v = make_float4(0.f, 0.f, 0.f, 0.f);
        if (row0 + row < M) v = *reinterpret_cast<const float4*>(src + (size_t)(row0 + row) * HDIM + c * 4);
        dst[row * KSTRIDE + c * 2 + 0] = pack_bf16(v.x, v.y);
        dst[row * KSTRIDE + c * 2 + 1] = pack_bf16(v.z, v.w);
    }
}

__device__ __forceinline__ float sigm(float x) { return 1.f / (1.f + expf(-x)); }
__device__ __forceinline__ float bf_lo(unsigned p) { return __uint_as_float(p << 16); }
__device__ __forceinline__ float bf_hi(unsigned p) { return __uint_as_float(p & 0xffff0000u); }

// ---------------- weight prepack ----------------
__global__ void k_pack(const float4* __restrict__ src, uint2* __restrict__ dst, int n4) {
    int i = blockIdx.x * blockDim.x + threadIdx.x;
    if (i < n4) {
        float4 v = src[i];
        dst[i] = make_uint2(pack_bf16(v.x, v.y), pack_bf16(v.z, v.w));
    }
}

// ---------------- CSR build ----------------
__global__ void k_deg_zero(int* deg, int n) {
    int i = blockIdx.x * blockDim.x + threadIdx.x;
    if (i < n) deg[i] = 0;
}

__global__ void k_hist(const int* __restrict__ dst, int* __restrict__ deg, int E) {
    int i = blockIdx.x * blockDim.x + threadIdx.x;
    if (i < E) atomicAdd(&deg[dst[i]], 1);
}

__global__ __launch_bounds__(SCAN_B) void k_scan_local(const int* __restrict__ deg,
                                                       int* __restrict__ rowptr,
                                                       int* __restrict__ blocksum, int n) {
    __shared__ int s[SCAN_B];
    int tid = threadIdx.x;
    int i = blockIdx.x * SCAN_B + tid;
    int v = (i < n) ? deg[i] : 0;
    s[tid] = v;
    __syncthreads();
    for (int off = 1; off < SCAN_B; off <<= 1) {
        int t = (tid >= off) ? s[tid - off] : 0;
        __syncthreads();
        s[tid] += t;
        __syncthreads();
    }
    if (i < n) rowptr[i] = s[tid] - v;
    if (tid == SCAN_B - 1) blocksum[blockIdx.x] = s[tid];
}

__global__ __launch_bounds__(256) void k_scan_block2(const int* __restrict__ blocksum,
                                                     int* __restrict__ blockoff,
                                                     int* __restrict__ rowptr, int nblk, int n) {
    __shared__ int s[256];
    int tid = threadIdx.x;
    int v = (tid < nblk) ? blocksum[tid] : 0;
    s[tid] = v;
    __syncthreads();
    for (int off = 1; off < 256; off <<= 1) {
        int t = (tid >= off) ? s[tid - off] : 0;
        __syncthreads();
        s[tid] += t;
        __syncthreads();
    }
    if (tid < nblk) blockoff[tid] = s[tid] - v;
    if (tid == 255) rowptr[n] = s[255];
}

__global__ void k_scan_add(int* __restrict__ rowptr, int* __restrict__ cursor,
                           const int* __restrict__ blockoff, int n) {
    int i = blockIdx.x * blockDim.x + threadIdx.x;
    if (i < n) {
        int v = rowptr[i] + blockoff[i / SCAN_B];
        rowptr[i] = v;
        cursor[i] = v;
    }
}

__global__ void k_scatter(const int* __restrict__ dst, const int* __restrict__ src,
                          const float* __restrict__ ew, int* __restrict__ cursor,
                          int2* __restrict__ csr_e, int E) {
    int i = blockIdx.x * blockDim.x + threadIdx.x;
    if (i < E) {
        int pos = atomicAdd(&cursor[dst[i]], 1);
        csr_e[pos] = make_int2(src[i], __float_as_int(ew[i]));
    }
}

// ---------------- SpMM (CSR, warp per node, 4-edge unrolled bf16 gather) ----------------
__global__ __launch_bounds__(256) void k_spmm_b(
    const int* __restrict__ rowptr, const int2* __restrict__ csr_e,
    const unsigned* __restrict__ xb, unsigned* __restrict__ aggb, int n) {
    int row = (blockIdx.x * blockDim.x + threadIdx.x) >> 5;
    int lane = threadIdx.x & 31;
    if (row >= n) return;
    int e = rowptr[row];
    int end = rowptr[row + 1];
    const uint2* x2 = reinterpret_cast<const uint2*>(xb);
    float a0 = 0.f, a1 = 0.f, a2 = 0.f, a3 = 0.f;
    int e4 = e + ((end - e) & ~3);
    for (; e < e4; e += 4) {
        int2 E0 = csr_e[e];
        int2 E1 = csr_e[e + 1];
        int2 E2 = csr_e[e + 2];
        int2 E3 = csr_e[e + 3];
        uint2 v0 = x2[(size_t)E0.x * 32 + lane];
        uint2 v1 = x2[(size_t)E1.x * 32 + lane];
        uint2 v2 = x2[(size_t)E2.x * 32 + lane];
        uint2 v3 = x2[(size_t)E3.x * 32 + lane];
        float w0 = __int_as_float(E0.y), w1 = __int_as_float(E1.y);
        float w2 = __int_as_float(E2.y), w3 = __int_as_float(E3.y);
        a0 = fmaf(w0, bf_lo(v0.x), a0); a1 = fmaf(w0, bf_hi(v0.x), a1);
        a2 = fmaf(w0, bf_lo(v0.y), a2); a3 = fmaf(w0, bf_hi(v0.y), a3);
        a0 = fmaf(w1, bf_lo(v1.x), a0); a1 = fmaf(w1, bf_hi(v1.x), a1);
        a2 = fmaf(w1, bf_lo(v1.y), a2); a3 = fmaf(w1, bf_hi(v1.y), a3);
        a0 = fmaf(w2, bf_lo(v2.x), a0); a1 = fmaf(w2, bf_hi(v2.x), a1);
        a2 = fmaf(w2, bf_lo(v2.y), a2); a3 = fmaf(w2, bf_hi(v2.y), a3);
        a0 = fmaf(w3, bf_lo(v3.x), a0); a1 = fmaf(w3, bf_hi(v3.x), a1);
        a2 = fmaf(w3, bf_lo(v3.y), a2); a3 = fmaf(w3, bf_hi(v3.y), a3);
    }
    for (; e < end; e++) {
        int2 E0 = csr_e[e];
        float w0 = __int_as_float(E0.y);
        uint2 v0 = x2[(size_t)E0.x * 32 + lane];
        a0 = fmaf(w0, bf_lo(v0.x), a0); a1 = fmaf(w0, bf_hi(v0.x), a1);
        a2 = fmaf(w0, bf_lo(v0.y), a2); a3 = fmaf(w0, bf_hi(v0.y), a3);
    }
    *reinterpret_cast<uint2*>(aggb + (size_t)row * 64 + lane * 2) =
        make_uint2(pack_bf16(a0, a1), pack_bf16(a2, a3));
}

// ---------------- mlp1 GEMM: xb = bf16(relu(features @ w1^T + b1)) ----------------
__global__ __launch_bounds__(256) void k_gemm_mlp1(
    const float* __restrict__ A, const float* __restrict__ W,
    const float* __restrict__ bias, unsigned* __restrict__ Cb, int M)
{
    extern __shared__ unsigned smem_u[];
    unsigned* As = smem_u;
    unsigned* Ws = smem_u + TILE_U32;

    const int tid = threadIdx.x;
    const int wid = tid >> 5;
    const int lane = tid & 31;
    const int g = lane >> 2;
    const int t4 = lane & 3;
    const int wm = wid & 3;
    const int wn = wid >> 2;
    const int m0 = blockIdx.x * 128;

    load_tile_g(As, A, m0, M, tid);
#pragma unroll
    for (int p = 0; p < 16; p++) {
        int F = p * 256 + tid;
        int row = F >> 5, c = F & 31;
        float4 v = *reinterpret_cast<const float4*>(W + (size_t)row * HDIM + c * 4);
        Ws[row * KSTRIDE + c * 2 + 0] = pack_bf16(v.x, v.y);
        Ws[row * KSTRIDE + c * 2 + 1] = pack_bf16(v.z, v.w);
    }
    __syncthreads();

    float acc[2][8][4];
#pragma unroll
    for (int i = 0; i < 2; i++) zero8(acc[i]);
    gemm128(As, Ws, acc, wm, wn, g, t4);

#pragma unroll
    for (int i = 0; i < 2; i++) {
        int row_lo = m0 + wm * 32 + i * 16 + g;
        int row_hi = row_lo + 8;
#pragma unroll
        for (int j = 0; j < 8; j++) {
            int col = wn * 64 + j * 8 + 2 * t4;
            float b0 = bias[col];
            float b1 = bias[col + 1];
            if (row_lo < M)
                Cb[(size_t)row_lo * 64 + (col >> 1)] =
                    pack_bf16(fmaxf(acc[i][j][0] + b0, 0.f), fmaxf(acc[i][j][1] + b1, 0.f));
            if (row_hi < M)
                Cb[(size_t)row_hi * 64 + (col >> 1)] =
                    pack_bf16(fmaxf(acc[i][j][2] + b0, 0.f), fmaxf(acc[i][j][3] + b1, 0.f));
        }
    }
}
#define GEMM_SMEM (2 * TILE_U32 * 4)

// ---------------- fused LAYER: GRU + GIN MLP + norm + head + softmax ----------------
// 64-row tiles, 2 CTA/SM, 9-chunk double-buffered weight stream, h never leaves smem
template <int C>
__global__ __launch_bounds__(256, 2) void k_layer(
    const unsigned* __restrict__ aggb, unsigned* xb,
    const unsigned* __restrict__ wihb, const unsigned* __restrict__ whhb,
    const float* __restrict__ bih, const float* __restrict__ bhh,
    const unsigned* __restrict__ g1b, const float* __restrict__ b1v,
    const unsigned* __restrict__ g2b, const float* __restrict__ b2v,
    const unsigned* __restrict__ hw1b, const float* __restrict__ hb1,
    const float* __restrict__ w2, const float* __restrict__ bh2,
    float* __restrict__ olog, float* __restrict__ osoft, int M)
{
    extern __shared__ unsigned sm[];
    unsigned* Aagg = sm;                          // agg tile -> h tile -> x tile
    unsigned* Ax   = sm + HTILE_U32;              // x tile -> t1/t2/logits
    unsigned* Wb0  = sm + 2 * HTILE_U32;
    unsigned* Wb1  = Wb0 + TILE_U32;
    unsigned* W2s  = Wb1 + TILE_U32;              // head w2 (24 rows)
    float* rowsum  = reinterpret_cast<float*>(W2s + 24 * KSTRIDE);  // [64]

    const int tid = threadIdx.x;
    const int wid = tid >> 5;
    const int lane = tid & 31;
    const int g = lane >> 2;
    const int t4 = lane & 3;
    const int wm = wid & 3;
    const int wn = wid >> 2;
    const int m0 = blockIdx.x * 64;

    if (tid < 64) rowsum[tid] = 0.f;

    // GRU chunk order: whh2(x), wih0(agg), whh0(x), wih2(agg), wih1(agg), whh1(x)
    cpa_tile64(Aagg, aggb, m0, M, tid);
    cpa_tile64(Ax,   xb,   m0, M, tid);
    cpa_tile(Wb0, whhb + 256 * 64, tid);
    cpa_commit();                                  // G0
    cpa_tile(Wb1, wihb, tid);
    cpa_commit();                                  // G1

    float accA[8][4], accB[8][4];
    zero8(accA); zero8(accB);

    // s2: accA = whh2 @ x
    cpa_wait1(); __syncthreads();
    gemm64(Ax, Wb0, accA, wm, wn, g, t4);
    __syncthreads();
    cpa_tile(Wb0, whhb, tid); cpa_commit();        // G2 = whh0

    // s3: accB = wih0 @ agg
    cpa_wait1(); __syncthreads();
    gemm64(Aagg, Wb1, accB, wm, wn, g, t4);
    __syncthreads();
    cpa_tile(Wb1, wihb + 256 * 64, tid); cpa_commit();  // G3 = wih2

    // s4: accB += whh0 @ x -> r; fold into n path
    cpa_wait1(); __syncthreads();
    gemm64(Ax, Wb0, accB, wm, wn, g, t4);
#pragma unroll
    for (int j = 0; j < 8; j++)
#pragma unroll
        for (int r = 0; r < 4; r++) {
            int col = wn * 64 + j * 8 + 2 * t4 + (r & 1);
            float rv = sigm(accB[j][r] + bih[col] + bhh[col]);
            accA[j][r] = rv * (accA[j][r] + bhh[256 + col]);
        }
    __syncthreads();
    cpa_tile(Wb0, wihb + 128 * 64, tid); cpa_commit();  // G4 = wih1

    // s5: accA += wih2 @ agg  (n preact)
    cpa_wait1(); __syncthreads();
    gemm64(Aagg, Wb1, accA, wm, wn, g, t4);
    __syncthreads();
    cpa_tile(Wb1, whhb + 128 * 64, tid); cpa_commit();  // G5 = whh1

    // s6: accB = wih1 @ agg
    zero8(accB);
    cpa_wait1(); __syncthreads();
    gemm64(Aagg, Wb0, accB, wm, wn, g, t4);
    __syncthreads();
    cpa_tile(Wb0, g1b, tid); cpa_commit();         // G6 = gin w1

    // s7: accB += whh1 @ x -> z ; h epilogue -> Aagg (smem only)
    cpa_wait1(); __syncthreads();
    gemm64(Ax, Wb1, accB, wm, wn, g, t4);
    {
        int rl_lo = wm * 16 + g;
        int rl_hi = rl_lo + 8;
#pragma unroll
        for (int j = 0; j < 8; j++) {
            int col = wn * 64 + j * 8 + 2 * t4;
            unsigned xp0 = Ax[rl_lo * KSTRIDE + (col >> 1)];
            unsigned xp1 = Ax[rl_hi * KSTRIDE + (col >> 1)];
            float z0 = sigm(accB[j][0] + bih[128 + col] + bhh[128 + col]);
            float z1 = sigm(accB[j][1] + bih[128 + col + 1] + bhh[128 + col + 1]);
            float z2 = sigm(accB[j][2] + bih[128 + col] + bhh[128 + col]);
            float z3 = sigm(accB[j][3] + bih[128 + col + 1] + bhh[128 + col + 1]);
            float n0 = tanhf(accA[j][0] + bih[256 + col]);
            float n1 = tanhf(accA[j][1] + bih[256 + col + 1]);
            float n2 = tanhf(accA[j][2] + bih[256 + col]);
            float n3 = tanhf(accA[j][3] + bih[256 + col + 1]);
            Aagg[rl_lo * KSTRIDE + (col >> 1)] =
                pack_bf16((1.f - z0) * n0 + z0 * bf_lo(xp0), (1.f - z1) * n1 + z1 * bf_hi(xp0));
            Aagg[rl_hi * KSTRIDE + (col >> 1)] =
                pack_bf16((1.f - z2) * n2 + z2 * bf_lo(xp1), (1.f - z3) * n3 + z3 * bf_hi(xp1));
        }
    }
    __syncthreads();
    cpa_tile(Wb1, g2b, tid); cpa_commit();         // G7 = gin w2

    // s8: t1 = relu(h @ g1^T + b1) -> Ax (t1 tile)
    zero8(accA);
    cpa_wait1(); __syncthreads();
    gemm64(Aagg, Wb0, accA, wm, wn, g, t4);
    {
        int rl = wm * 16 + g;
#pragma unroll
        for (int j = 0; j < 8; j++) {
            int col = wn * 64 + j * 8 + 2 * t4;
            Ax[rl * KSTRIDE + (col >> 1)] =
                pack_bf16(fmaxf(accA[j][0] + b1v[col], 0.f), fmaxf(accA[j][1] + b1v[col + 1], 0.f));
            Ax[(rl + 8) * KSTRIDE + (col >> 1)] =
                pack_bf16(fmaxf(accA[j][2] + b1v[col], 0.f), fmaxf(accA[j][3] + b1v[col + 1], 0.f));
        }
    }
    __syncthreads();
    cpa_tile(Wb0, hw1b, tid); cpa_commit();        // G8 = head w1

    // s9: x = relu(t1 @ g2^T + b2); rowsum; normalize; write xb; repack to Aagg; load W2s
    zero8(accA);
    cpa_wait1(); __syncthreads();
    gemm64(Ax, Wb1, accA, wm, wn, g, t4);
    {
        float s_lo = 0.f, s_hi = 0.f;
#pragma unroll
        for (int j = 0; j < 8; j++) {
            int col = wn * 64 + j * 8 + 2 * t4;
            accA[j][0] = fmaxf(accA[j][0] + b2v[col], 0.f);
            accA[j][1] = fmaxf(accA[j][1] + b2v[col + 1], 0.f);
            accA[j][2] = fmaxf(accA[j][2] + b2v[col], 0.f);
            accA[j][3] = fmaxf(accA[j][3] + b2v[col + 1], 0.f);
            s_lo += accA[j][0] * accA[j][0] + accA[j][1] * accA[j][1];
            s_hi += accA[j][2] * accA[j][2] + accA[j][3] * accA[j][3];
        }
        atomicAdd(&rowsum[wm * 16 + g], s_lo);
        atomicAdd(&rowsum[wm * 16 + 8 + g], s_hi);
    }
    __syncthreads();
    {
        int rl = wm * 16 + g;
        float inv_lo = rsqrtf(1.f + rowsum[rl]);
        float inv_hi = rsqrtf(1.f + rowsum[rl + 8]);
        int gm_lo = m0 + rl;
        int gm_hi = gm_lo + 8;
#pragma unroll
        for (int j = 0; j < 8; j++) {
            int col = wn * 64 + j * 8 + 2 * t4;
            unsigned p_lo = pack_bf16(accA[j][0] * inv_lo, accA[j][1] * inv_lo);
            unsigned p_hi = pack_bf16(accA[j][2] * inv_hi, accA[j][3] * inv_hi);
            Aagg[rl * KSTRIDE + (col >> 1)] = p_lo;
            Aagg[(rl + 8) * KSTRIDE + (col >> 1)] = p_hi;
            if (gm_lo < M) xb[(size_t)gm_lo * 64 + (col >> 1)] = p_lo;
            if (gm_hi < M) xb[(size_t)gm_hi * 64 + (col >> 1)] = p_hi;
        }
    }
    for (int idx = tid; idx < 24 * 32; idx += 256) {
        int row = idx >> 5, c = idx & 31;
        float4 v = make_float4(0.f, 0.f, 0.f, 0.f);
        if (row < C) v = *reinterpret_cast<const float4*>(w2 + (size_t)row * HDIM + c * 4);
        W2s[row * KSTRIDE + c * 2 + 0] = pack_bf16(v.x, v.y);
        W2s[row * KSTRIDE + c * 2 + 1] = pack_bf16(v.z, v.w);
    }
    __syncthreads();

    // s10: t2 = relu(x @ hw1^T + hb1) -> Ax
    zero8(accA);
    cpa_wait0(); __syncthreads();
    gemm64(Aagg, Wb0, accA, wm, wn, g, t4);
    {
        int rl = wm * 16 + g;
#pragma unroll
        for (int j = 0; j < 8; j++) {
            int col = wn * 64 + j * 8 + 2 * t4;
            Ax[rl * KSTRIDE + (col >> 1)] =
                pack_bf16(fmaxf(accA[j][0] + hb1[col], 0.f), fmaxf(accA[j][1] + hb1[col + 1], 0.f));
            Ax[(rl + 8) * KSTRIDE + (col >> 1)] =
                pack_bf16(fmaxf(accA[j][2] + hb1[col], 0.f), fmaxf(accA[j][3] + hb1[col + 1], 0.f));
        }
    }
    __syncthreads();

    // s11: head logits (wn==0 warps), softmax
    float hacc[3][4];
#pragma unroll
    for (int j = 0; j < 3; j++)
#pragma unroll
        for (int r = 0; r < 4; r++) hacc[j][r] = 0.f;
    if (wn == 0) {
#pragma unroll
        for (int ks = 0; ks < 8; ks++) {
            int kb = ks * 8;
            int rb = wm * 16;
            unsigned af[4];
            af[0] = Ax[(rb + g) * KSTRIDE + kb + t4];
            af[1] = Ax[(rb + 8 + g) * KSTRIDE + kb + t4];
            af[2] = Ax[(rb + g) * KSTRIDE + kb + t4 + 4];
            af[3] = Ax[(rb + 8 + g) * KSTRIDE + kb + t4 + 4];
            unsigned bfr[3][2];
#pragma unroll
            for (int j = 0; j < 3; j++) {
                int nb = j * 8;
                bfr[j][0] = W2s[(nb + g) * KSTRIDE + kb + t4];
                bfr[j][1] = W2s[(nb + g) * KSTRIDE + kb + t4 + 4];
            }
#pragma unroll
            for (int j = 0; j < 3; j++)
                mma_bf16(hacc[j], af, bfr[j]);
        }
    }
    __syncthreads();
    float* logitp = reinterpret_cast<float*>(Ax);   // [64][28]
    if (wn == 0) {
        int rl = wm * 16 + g;
#pragma unroll
        for (int j = 0; j < 3; j++) {
            int col = j * 8 + 2 * t4;
            logitp[rl * 28 + col] = hacc[j][0];
            logitp[rl * 28 + col + 1] = hacc[j][1];
            logitp[(rl + 8) * 28 + col] = hacc[j][2];
            logitp[(rl + 8) * 28 + col + 1] = hacc[j][3];
        }
    }
    __syncthreads();

#pragma unroll
    for (int k = 0; k < 8; k++) {
        int nl = wid * 8 + k;
        int gm = m0 + nl;
        float myval = (lane < C) ? (logitp[nl * 28 + lane] + bh2[lane]) : 0.f;
        float mx = (lane < C) ? myval : -INFINITY;
#pragma unroll
        for (int o = 16; o; o >>= 1) mx = fmaxf(mx, __shfl_xor_sync(0xffffffffu, mx, o));
        float e = (lane < C) ? expf(myval - mx) : 0.f;
        float s = e;
#pragma unroll
        for (int o = 16; o; o >>= 1) s += __shfl_xor_sync(0xffffffffu, s, o);
        if (gm < M && lane < C) {
            olog [(size_t)gm * C + lane] = myval - mx - logf(s);
            osoft[(size_t)gm * C + lane] = e / s;
        }
    }
}
#define LAYER_SMEM ((2 * HTILE_U32 + 2 * TILE_U32 + 24 * KSTRIDE + 64) * 4)

// ---------------- launch ----------------
extern "C" void kernel_launch(void* const* d_in, const int* in_sizes, int n_in,
                              void* d_out, int out_size) {
    const float* features = (const float*)d_in[0];
    const int*   eidx     = (const int*)  d_in[1];
    const float* ew       = (const float*)d_in[2];
    const float* w1       = (const float*)d_in[3];
    const float* b1       = (const float*)d_in[4];
    const float* gin_w1   = (const float*)d_in[5];
    const float* gin_b1   = (const float*)d_in[6];
    const float* gin_w2   = (const float*)d_in[7];
    const float* gin_b2   = (const float*)d_in[8];
    const float* gru_wih  = (const float*)d_in[9];
    const float* gru_whh  = (const float*)d_in[10];
    const float* gru_bih  = (const float*)d_in[11];
    const float* gru_bhh  = (const float*)d_in[12];
    const float* head_w1  = (const float*)d_in[13];
    const float* head_b1  = (const float*)d_in[14];
    const float* hw2_0    = (const float*)d_in[15];
    const float* hb2_0    = (const float*)d_in[16];
    const float* hw2_1    = (const float*)d_in[17];
    const float* hb2_1    = (const float*)d_in[18];
    const float* hw2_2    = (const float*)d_in[19];
    const float* hb2_2    = (const float*)d_in[20];

    float* out = (float*)d_out;

    unsigned *p_xb, *p_aggb, *p_wb;
    int2 *p_csr_e;
    int *p_rowptr, *p_cursor, *p_bsum, *p_boff;
    cudaGetSymbolAddress((void**)&p_xb,     g_xb);
    cudaGetSymbolAddress((void**)&p_aggb,   g_aggb);
    cudaGetSymbolAddress((void**)&p_wb,     g_wb);
    cudaGetSymbolAddress((void**)&p_rowptr, g_rowptr);
    cudaGetSymbolAddress((void**)&p_cursor, g_cursor);
    cudaGetSymbolAddress((void**)&p_bsum,   g_blocksum);
    cudaGetSymbolAddress((void**)&p_boff,   g_blockoff);
    cudaGetSymbolAddress((void**)&p_csr_e,  g_csr_e);

    cudaFuncSetAttribute(k_gemm_mlp1,  cudaFuncAttributeMaxDynamicSharedMemorySize, GEMM_SMEM);
    cudaFuncSetAttribute(k_layer<2>,   cudaFuncAttributeMaxDynamicSharedMemorySize, LAYER_SMEM);
    cudaFuncSetAttribute(k_layer<6>,   cudaFuncAttributeMaxDynamicSharedMemorySize, LAYER_SMEM);
    cudaFuncSetAttribute(k_layer<21>,  cudaFuncAttributeMaxDynamicSharedMemorySize, LAYER_SMEM);

    const int M = NNODES;
    const int E = NEDGES;
    const int tile_gx   = (M + 127) / 128;   // 782
    const int tile64_gx = (M + 63) / 64;     // 1563
    const int warp_blocks = (M * 32 + 255) / 256;
    const int edge_blocks = (E + 255) / 256;
    const int node_blocks = (M + 255) / 256;

    const int* e_dst = eidx;
    const int* e_src = eidx + E;

    const size_t o_log0 = 0;
    const size_t o_log1 = (size_t)M * 2;
    const size_t o_log2 = (size_t)M * 8;
    const size_t o_soft = (size_t)M * 29;

    // ---- prepack weights to bf16 ----
    {
        int n4;
        n4 = 3 * 384 * HDIM / 4;
        k_pack<<<(n4 + 255) / 256, 256>>>((const float4*)gru_wih, (uint2*)(p_wb + OFF_WIH), n4);
        k_pack<<<(n4 + 255) / 256, 256>>>((const float4*)gru_whh, (uint2*)(p_wb + OFF_WHH), n4);
        n4 = 3 * HDIM * HDIM / 4;
        k_pack<<<(n4 + 255) / 256, 256>>>((const float4*)gin_w1,  (uint2*)(p_wb + OFF_GW1), n4);
        k_pack<<<(n4 + 255) / 256, 256>>>((const float4*)gin_w2,  (uint2*)(p_wb + OFF_GW2), n4);
        k_pack<<<(n4 + 255) / 256, 256>>>((const float4*)head_w1, (uint2*)(p_wb + OFF_HW1), n4);
    }

    // ---- build CSR ----
    k_deg_zero<<<node_blocks, 256>>>(p_cursor, M);
    k_hist<<<edge_blocks, 256>>>(e_dst, p_cursor, E);
    k_scan_local<<<NSCANB, SCAN_B>>>(p_cursor, p_rowptr, p_bsum, M);
    k_scan_block2<<<1, 256>>>(p_bsum, p_boff, p_rowptr, NSCANB, M);
    k_scan_add<<<node_blocks, 256>>>(p_rowptr, p_cursor, p_boff, M);
    k_scatter<<<edge_blocks, 256>>>(e_dst, e_src, ew, p_cursor, p_csr_e, E);

    // x = relu(features @ w1^T + b1)  (bf16)
    k_gemm_mlp1<<<tile_gx, 256, GEMM_SMEM>>>(features, w1, b1, p_xb, M);

    for (int i = 0; i < NL; i++) {
        k_spmm_b<<<warp_blocks, 256>>>(p_rowptr, p_csr_e, p_xb, p_aggb, M);

        const unsigned* wihb = p_wb + OFF_WIH + (size_t)i * 384 * 64;
        const unsigned* whhb = p_wb + OFF_WHH + (size_t)i * 384 * 64;
        const unsigned* g1b  = p_wb + OFF_GW1 + (size_t)i * 128 * 64;
        const unsigned* g2b  = p_wb + OFF_GW2 + (size_t)i * 128 * 64;
        const unsigned* hw1b = p_wb + OFF_HW1 + (size_t)i * 128 * 64;
        const float* bih = gru_bih + (size_t)i * 384;
        const float* bhh = gru_bhh + (size_t)i * 384;

        if (i == 0)
            k_layer<2><<<tile64_gx, 256, LAYER_SMEM>>>(
                p_aggb, p_xb, wihb, whhb, bih, bhh,
                g1b, gin_b1, g2b, gin_b2, hw1b, head_b1, hw2_0, hb2_0,
                out + o_log0, out + o_soft, M);
        else if (i == 1)
            k_layer<6><<<tile64_gx, 256, LAYER_SMEM>>>(
                p_aggb, p_xb, wihb, whhb, bih, bhh,
                g1b, gin_b1 + HDIM, g2b, gin_b2 + HDIM,
                hw1b, head_b1 + HDIM, hw2_1, hb2_1,
                out + o_log1, out + o_soft + (size_t)M * 2, M);
        else
            k_layer<21><<<tile64_gx, 256, LAYER_SMEM>>>(
                p_aggb, p_xb, wihb, whhb, bih, bhh,
                g1b, gin_b1 + 2 * HDIM, g2b, gin_b2 + 2 * HDIM,
                hw1b, head_b1 + 2 * HDIM, hw2_2, hb2_2,
                out + o_log2, out + o_soft + (size_t)M * 8, M);
    }
}

// round 13
// speedup vs baseline: 1.6048x; 1.0260x over previous
#include <cuda_runtime.h>
#include <cuda_bf16.h>
#include <math.h>

#define NNODES 100000
#define NEDGES 1600000
#define HDIM   128
#define NL     3
#define SCAN_B 512
#define NSCANB ((NNODES + SCAN_B - 1) / SCAN_B)   // 196

#define KSTRIDE 68                 // smem row stride in u32 (64 bf16-pairs + pad 4)
#define TILE_U32 (128 * KSTRIDE)   // 128-row bf16 tile in u32
#define HTILE_U32 (64 * KSTRIDE)   // 64-row bf16 tile in u32

// prepacked bf16 weight buffer offsets (u32 units)
#define OFF_WIH 0
#define OFF_WHH (OFF_WIH + 3 * 384 * 64)
#define OFF_GW1 (OFF_WHH + 3 * 384 * 64)
#define OFF_GW2 (OFF_GW1 + 3 * 128 * 64)
#define OFF_HW1 (OFF_GW2 + 3 * 128 * 64)
#define WB_TOTAL (OFF_HW1 + 3 * 128 * 64)

// pack segment sizes in float4 units
#define N4_GRU (3 * 384 * HDIM / 4)   // 36864
#define N4_GIN (3 * HDIM * HDIM / 4)  // 12288
#define SETUP_TOTAL (2 * N4_GRU + 3 * N4_GIN + NNODES)

// ---------------- scratch (no allocations allowed) ----------------
__device__ unsigned g_xb  [(size_t)NNODES * 64];        // bf16 x
__device__ unsigned g_aggb[(size_t)NNODES * 64];        // bf16 agg
__device__ unsigned g_wb  [WB_TOTAL];                   // prepacked weights
// CSR scratch
__device__ int   g_rowptr[NNODES + 1];
__device__ int   g_cursor[NNODES];
__device__ int   g_blocksum[NSCANB];
__device__ int   g_blockoff[NSCANB];
__device__ int2  g_csr_e[NEDGES];                       // {src, w_bits}

// ---------------- helpers ----------------
__device__ __forceinline__ unsigned pack_bf16(float a, float b) {
    __nv_bfloat162 t = __floats2bfloat162_rn(a, b);
    return *reinterpret_cast<unsigned*>(&t);
}

__device__ __forceinline__ void mma_bf16(float* d, const unsigned* a, const unsigned* b) {
    asm volatile(
        "mma.sync.aligned.m16n8k16.row.col.f32.bf16.bf16.f32 "
        "{%0,%1,%2,%3}, {%4,%5,%6,%7}, {%8,%9}, {%0,%1,%2,%3};\n"
        : "+f"(d[0]), "+f"(d[1]), "+f"(d[2]), "+f"(d[3])
        : "r"(a[0]), "r"(a[1]), "r"(a[2]), "r"(a[3]), "r"(b[0]), "r"(b[1]));
}

__device__ __forceinline__ void cpa16(unsigned* smem_dst, const unsigned* g, bool valid) {
    unsigned saddr = (unsigned)__cvta_generic_to_shared(smem_dst);
    int sz = valid ? 16 : 0;
    asm volatile("cp.async.cg.shared.global [%0], [%1], 16, %2;\n"
                 :: "r"(saddr), "l"(g), "r"(sz) : "memory");
}
__device__ __forceinline__ void cpa_commit() {
    asm volatile("cp.async.commit_group;\n" ::: "memory");
}
__device__ __forceinline__ void cpa_wait0() {
    asm volatile("cp.async.wait_group 0;\n" ::: "memory");
}
__device__ __forceinline__ void cpa_wait1() {
    asm volatile("cp.async.wait_group 1;\n" ::: "memory");
}

// 128-row tile async copy (weights)
__device__ __forceinline__ void cpa_tile(unsigned* dst, const unsigned* __restrict__ src,
                                         int tid) {
#pragma unroll
    for (int p = 0; p < 8; p++) {
        int F = p * 256 + tid;
        int row = F >> 4;
        int c4 = (F & 15) * 4;
        cpa16(dst + row * KSTRIDE + c4, src + (size_t)row * 64 + c4, true);
    }
}

// 64-row tile async copy (activations), OOB rows zero-filled
__device__ __forceinline__ void cpa_tile64(unsigned* dst, const unsigned* __restrict__ src,
                                           int row0, int Mrows, int tid) {
#pragma unroll
    for (int p = 0; p < 4; p++) {
        int F = p * 256 + tid;
        int row = F >> 4;
        int c4 = (F & 15) * 4;
        bool v = (row0 + row) < Mrows;
        cpa16(dst + row * KSTRIDE + c4, src + (size_t)(row0 + row) * 64 + c4, v);
    }
}

// acc += A64 @ W128^T for this warp (64-row A tile)
__device__ __forceinline__ void gemm64(const unsigned* __restrict__ As,
                                       const unsigned* __restrict__ Ws,
                                       float acc[8][4],
                                       int wm, int wn, int g, int t4) {
#pragma unroll
    for (int ks = 0; ks < 8; ks++) {
        int kb = ks * 8;
        int rb = wm * 16;
        unsigned af[4];
        af[0] = As[(rb + g) * KSTRIDE + kb + t4];
        af[1] = As[(rb + 8 + g) * KSTRIDE + kb + t4];
        af[2] = As[(rb + g) * KSTRIDE + kb + t4 + 4];
        af[3] = As[(rb + 8 + g) * KSTRIDE + kb + t4 + 4];
        unsigned bf[8][2];
#pragma unroll
        for (int j = 0; j < 8; j++) {
            int nb = wn * 64 + j * 8;
            bf[j][0] = Ws[(nb + g) * KSTRIDE + kb + t4];
            bf[j][1] = Ws[(nb + g) * KSTRIDE + kb + t4 + 4];
        }
#pragma unroll
        for (int j = 0; j < 8; j++)
            mma_bf16(acc[j], af, bf[j]);
    }
}

// 128-row variant (mlp1)
__device__ __forceinline__ void gemm128(const unsigned* __restrict__ As,
                                        const unsigned* __restrict__ Ws,
                                        float acc[2][8][4],
                                        int wm, int wn, int g, int t4) {
#pragma unroll
    for (int ks = 0; ks < 8; ks++) {
        int kb = ks * 8;
        unsigned af[2][4];
#pragma unroll
        for (int i = 0; i < 2; i++) {
            int rb = wm * 32 + i * 16;
            af[i][0] = As[(rb + g) * KSTRIDE + kb + t4];
            af[i][1] = As[(rb + 8 + g) * KSTRIDE + kb + t4];
            af[i][2] = As[(rb + g) * KSTRIDE + kb + t4 + 4];
            af[i][3] = As[(rb + 8 + g) * KSTRIDE + kb + t4 + 4];
        }
        unsigned bf[8][2];
#pragma unroll
        for (int j = 0; j < 8; j++) {
            int nb = wn * 64 + j * 8;
            bf[j][0] = Ws[(nb + g) * KSTRIDE + kb + t4];
            bf[j][1] = Ws[(nb + g) * KSTRIDE + kb + t4 + 4];
        }
#pragma unroll
        for (int i = 0; i < 2; i++)
#pragma unroll
            for (int j = 0; j < 8; j++)
                mma_bf16(acc[i][j], af[i], bf[j]);
    }
}

__device__ __forceinline__ void zero8(float acc[8][4]) {
#pragma unroll
    for (int j = 0; j < 8; j++)
#pragma unroll
        for (int r = 0; r < 4; r++) acc[j][r] = 0.f;
}

// load 128x128 f32 tile -> bf16 smem (mlp1 features / weights)
__device__ __forceinline__ void load_tile_g(unsigned* dst, const float* __restrict__ src,
                                            int row0, int M, int tid) {
#pragma unroll
    for (int p = 0; p < 16; p++) {
        int F = p * 256 + tid;
        int row = F >> 5, c = F & 31;
        float4 v = make_float4(0.f, 0.f, 0.f, 0.f);
        if (row0 + row < M) v = *reinterpret_cast<const float4*>(src + (size_t)(row0 + row) * HDIM + c * 4);
        dst[row * KSTRIDE + c * 2 + 0] = pack_bf16(v.x, v.y);
        dst[row * KSTRIDE + c * 2 + 1] = pack_bf16(v.z, v.w);
    }
}

__device__ __forceinline__ float sigm(float x) { return 1.f / (1.f + expf(-x)); }
__device__ __forceinline__ float bf_lo(unsigned p) { return __uint_as_float(p << 16); }
__device__ __forceinline__ float bf_hi(unsigned p) { return __uint_as_float(p & 0xffff0000u); }

// ---------------- fused setup: pack all weights + zero degree counters ----------------
__global__ void k_setup(const float4* __restrict__ wih, const float4* __restrict__ whh,
                        const float4* __restrict__ gw1, const float4* __restrict__ gw2,
                        const float4* __restrict__ hw1,
                        uint2* __restrict__ wb, int* __restrict__ deg) {
    int i = blockIdx.x * blockDim.x + threadIdx.x;
    if (i >= SETUP_TOTAL) return;
    const float4* src;
    uint2* dst;
    int idx = i;
    if (idx < N4_GRU) { src = wih; dst = wb + OFF_WIH / 2; }
    else if ((idx -= N4_GRU) < N4_GRU) { src = whh; dst = wb + OFF_WHH / 2; }
    else if ((idx -= N4_GRU) < N4_GIN) { src = gw1; dst = wb + OFF_GW1 / 2; }
    else if ((idx -= N4_GIN) < N4_GIN) { src = gw2; dst = wb + OFF_GW2 / 2; }
    else if ((idx -= N4_GIN) < N4_GIN) { src = hw1; dst = wb + OFF_HW1 / 2; }
    else { deg[idx - N4_GIN] = 0; return; }
    float4 v = src[idx];
    dst[idx] = make_uint2(pack_bf16(v.x, v.y), pack_bf16(v.z, v.w));
}

// ---------------- CSR build ----------------
__global__ void k_hist(const int* __restrict__ dst, int* __restrict__ deg, int E) {
    int i = blockIdx.x * blockDim.x + threadIdx.x;
    if (i < E) atomicAdd(&deg[dst[i]], 1);
}

__global__ __launch_bounds__(SCAN_B) void k_scan_local(const int* __restrict__ deg,
                                                       int* __restrict__ rowptr,
                                                       int* __restrict__ blocksum, int n) {
    __shared__ int s[SCAN_B];
    int tid = threadIdx.x;
    int i = blockIdx.x * SCAN_B + tid;
    int v = (i < n) ? deg[i] : 0;
    s[tid] = v;
    __syncthreads();
    for (int off = 1; off < SCAN_B; off <<= 1) {
        int t = (tid >= off) ? s[tid - off] : 0;
        __syncthreads();
        s[tid] += t;
        __syncthreads();
    }
    if (i < n) rowptr[i] = s[tid] - v;
    if (tid == SCAN_B - 1) blocksum[blockIdx.x] = s[tid];
}

__global__ __launch_bounds__(256) void k_scan_block2(const int* __restrict__ blocksum,
                                                     int* __restrict__ blockoff,
                                                     int* __restrict__ rowptr, int nblk, int n) {
    __shared__ int s[256];
    int tid = threadIdx.x;
    int v = (tid < nblk) ? blocksum[tid] : 0;
    s[tid] = v;
    __syncthreads();
    for (int off = 1; off < 256; off <<= 1) {
        int t = (tid >= off) ? s[tid - off] : 0;
        __syncthreads();
        s[tid] += t;
        __syncthreads();
    }
    if (tid < nblk) blockoff[tid] = s[tid] - v;
    if (tid == 255) rowptr[n] = s[255];
}

__global__ void k_scan_add(int* __restrict__ rowptr, int* __restrict__ cursor,
                           const int* __restrict__ blockoff, int n) {
    int i = blockIdx.x * blockDim.x + threadIdx.x;
    if (i < n) {
        int v = rowptr[i] + blockoff[i / SCAN_B];
        rowptr[i] = v;
        cursor[i] = v;
    }
}

__global__ void k_scatter(const int* __restrict__ dst, const int* __restrict__ src,
                          const float* __restrict__ ew, int* __restrict__ cursor,
                          int2* __restrict__ csr_e, int E) {
    int i = blockIdx.x * blockDim.x + threadIdx.x;
    if (i < E) {
        int pos = atomicAdd(&cursor[dst[i]], 1);
        csr_e[pos] = make_int2(src[i], __float_as_int(ew[i]));
    }
}

// ---------------- SpMM (CSR, warp per node, int4 edge-pair loads) ----------------
__global__ __launch_bounds__(256) void k_spmm_b(
    const int* __restrict__ rowptr, const int2* __restrict__ csr_e,
    const unsigned* __restrict__ xb, unsigned* __restrict__ aggb, int n) {
    int row = (blockIdx.x * blockDim.x + threadIdx.x) >> 5;
    int lane = threadIdx.x & 31;
    if (row >= n) return;
    int e = rowptr[row];
    int end = rowptr[row + 1];
    const uint2* x2 = reinterpret_cast<const uint2*>(xb);
    float a0 = 0.f, a1 = 0.f, a2 = 0.f, a3 = 0.f;
    // align to pair boundary
    if ((e & 1) && e < end) {
        int2 E0 = csr_e[e];
        float w0 = __int_as_float(E0.y);
        uint2 v0 = x2[(size_t)E0.x * 32 + lane];
        a0 = fmaf(w0, bf_lo(v0.x), a0); a1 = fmaf(w0, bf_hi(v0.x), a1);
        a2 = fmaf(w0, bf_lo(v0.y), a2); a3 = fmaf(w0, bf_hi(v0.y), a3);
        e++;
    }
    const int4* e2 = reinterpret_cast<const int4*>(csr_e);
    int np = (end - e) >> 1;   // pairs
    int p = e >> 1;
    for (; np >= 2; np -= 2, p += 2) {
        int4 P0 = e2[p];
        int4 P1 = e2[p + 1];
        uint2 v0 = x2[(size_t)P0.x * 32 + lane];
        uint2 v1 = x2[(size_t)P0.z * 32 + lane];
        uint2 v2 = x2[(size_t)P1.x * 32 + lane];
        uint2 v3 = x2[(size_t)P1.z * 32 + lane];
        float w0 = __int_as_float(P0.y), w1 = __int_as_float(P0.w);
        float w2 = __int_as_float(P1.y), w3 = __int_as_float(P1.w);
        a0 = fmaf(w0, bf_lo(v0.x), a0); a1 = fmaf(w0, bf_hi(v0.x), a1);
        a2 = fmaf(w0, bf_lo(v0.y), a2); a3 = fmaf(w0, bf_hi(v0.y), a3);
        a0 = fmaf(w1, bf_lo(v1.x), a0); a1 = fmaf(w1, bf_hi(v1.x), a1);
        a2 = fmaf(w1, bf_lo(v1.y), a2); a3 = fmaf(w1, bf_hi(v1.y), a3);
        a0 = fmaf(w2, bf_lo(v2.x), a0); a1 = fmaf(w2, bf_hi(v2.x), a1);
        a2 = fmaf(w2, bf_lo(v2.y), a2); a3 = fmaf(w2, bf_hi(v2.y), a3);
        a0 = fmaf(w3, bf_lo(v3.x), a0); a1 = fmaf(w3, bf_hi(v3.x), a1);
        a2 = fmaf(w3, bf_lo(v3.y), a2); a3 = fmaf(w3, bf_hi(v3.y), a3);
    }
    if (np) {
        int4 P0 = e2[p];
        uint2 v0 = x2[(size_t)P0.x * 32 + lane];
        uint2 v1 = x2[(size_t)P0.z * 32 + lane];
        float w0 = __int_as_float(P0.y), w1 = __int_as_float(P0.w);
        a0 = fmaf(w0, bf_lo(v0.x), a0); a1 = fmaf(w0, bf_hi(v0.x), a1);
        a2 = fmaf(w0, bf_lo(v0.y), a2); a3 = fmaf(w0, bf_hi(v0.y), a3);
        a0 = fmaf(w1, bf_lo(v1.x), a0); a1 = fmaf(w1, bf_hi(v1.x), a1);
        a2 = fmaf(w1, bf_lo(v1.y), a2); a3 = fmaf(w1, bf_hi(v1.y), a3);
        p++;
    }
    if ((end - e) & 1 && false) {}
    // leftover single edge at the tail (when (end-e) odd)
    if (((end - (e & ~0)) & 1) == 1) {
        int2 E0 = csr_e[end - 1];
        float w0 = __int_as_float(E0.y);
        uint2 v0 = x2[(size_t)E0.x * 32 + lane];
        a0 = fmaf(w0, bf_lo(v0.x), a0); a1 = fmaf(w0, bf_hi(v0.x), a1);
        a2 = fmaf(w0, bf_lo(v0.y), a2); a3 = fmaf(w0, bf_hi(v0.y), a3);
    }
    *reinterpret_cast<uint2*>(aggb + (size_t)row * 64 + lane * 2) =
        make_uint2(pack_bf16(a0, a1), pack_bf16(a2, a3));
}

// ---------------- mlp1 GEMM: xb = bf16(relu(features @ w1^T + b1)) ----------------
__global__ __launch_bounds__(256) void k_gemm_mlp1(
    const float* __restrict__ A, const float* __restrict__ W,
    const float* __restrict__ bias, unsigned* __restrict__ Cb, int M)
{
    extern __shared__ unsigned smem_u[];
    unsigned* As = smem_u;
    unsigned* Ws = smem_u + TILE_U32;

    const int tid = threadIdx.x;
    const int wid = tid >> 5;
    const int lane = tid & 31;
    const int g = lane >> 2;
    const int t4 = lane & 3;
    const int wm = wid & 3;
    const int wn = wid >> 2;
    const int m0 = blockIdx.x * 128;

    load_tile_g(As, A, m0, M, tid);
#pragma unroll
    for (int p = 0; p < 16; p++) {
        int F = p * 256 + tid;
        int row = F >> 5, c = F & 31;
        float4 v = *reinterpret_cast<const float4*>(W + (size_t)row * HDIM + c * 4);
        Ws[row * KSTRIDE + c * 2 + 0] = pack_bf16(v.x, v.y);
        Ws[row * KSTRIDE + c * 2 + 1] = pack_bf16(v.z, v.w);
    }
    __syncthreads();

    float acc[2][8][4];
#pragma unroll
    for (int i = 0; i < 2; i++) zero8(acc[i]);
    gemm128(As, Ws, acc, wm, wn, g, t4);

#pragma unroll
    for (int i = 0; i < 2; i++) {
        int row_lo = m0 + wm * 32 + i * 16 + g;
        int row_hi = row_lo + 8;
#pragma unroll
        for (int j = 0; j < 8; j++) {
            int col = wn * 64 + j * 8 + 2 * t4;
            float b0 = bias[col];
            float b1 = bias[col + 1];
            if (row_lo < M)
                Cb[(size_t)row_lo * 64 + (col >> 1)] =
                    pack_bf16(fmaxf(acc[i][j][0] + b0, 0.f), fmaxf(acc[i][j][1] + b1, 0.f));
            if (row_hi < M)
                Cb[(size_t)row_hi * 64 + (col >> 1)] =
                    pack_bf16(fmaxf(acc[i][j][2] + b0, 0.f), fmaxf(acc[i][j][3] + b1, 0.f));
        }
    }
}
#define GEMM_SMEM (2 * TILE_U32 * 4)

// ---------------- fused LAYER: GRU + GIN MLP + norm + head + softmax ----------------
template <int C>
__global__ __launch_bounds__(256, 2) void k_layer(
    const unsigned* __restrict__ aggb, unsigned* xb,
    const unsigned* __restrict__ wihb, const unsigned* __restrict__ whhb,
    const float* __restrict__ bih, const float* __restrict__ bhh,
    const unsigned* __restrict__ g1b, const float* __restrict__ b1v,
    const unsigned* __restrict__ g2b, const float* __restrict__ b2v,
    const unsigned* __restrict__ hw1b, const float* __restrict__ hb1,
    const float* __restrict__ w2, const float* __restrict__ bh2,
    float* __restrict__ olog, float* __restrict__ osoft, int M)
{
    extern __shared__ unsigned sm[];
    unsigned* Aagg = sm;                          // agg tile -> h tile -> x tile
    unsigned* Ax   = sm + HTILE_U32;              // x tile -> t1/t2/logits
    unsigned* Wb0  = sm + 2 * HTILE_U32;
    unsigned* Wb1  = Wb0 + TILE_U32;
    unsigned* W2s  = Wb1 + TILE_U32;              // head w2 (24 rows)
    float* rowsum  = reinterpret_cast<float*>(W2s + 24 * KSTRIDE);  // [64]

    const int tid = threadIdx.x;
    const int wid = tid >> 5;
    const int lane = tid & 31;
    const int g = lane >> 2;
    const int t4 = lane & 3;
    const int wm = wid & 3;
    const int wn = wid >> 2;
    const int m0 = blockIdx.x * 64;

    if (tid < 64) rowsum[tid] = 0.f;

    cpa_tile64(Aagg, aggb, m0, M, tid);
    cpa_tile64(Ax,   xb,   m0, M, tid);
    cpa_tile(Wb0, whhb + 256 * 64, tid);
    cpa_commit();                                  // G0
    cpa_tile(Wb1, wihb, tid);
    cpa_commit();                                  // G1

    float accA[8][4], accB[8][4];
    zero8(accA); zero8(accB);

    // s2: accA = whh2 @ x
    cpa_wait1(); __syncthreads();
    gemm64(Ax, Wb0, accA, wm, wn, g, t4);
    __syncthreads();
    cpa_tile(Wb0, whhb, tid); cpa_commit();        // G2 = whh0

    // s3: accB = wih0 @ agg
    cpa_wait1(); __syncthreads();
    gemm64(Aagg, Wb1, accB, wm, wn, g, t4);
    __syncthreads();
    cpa_tile(Wb1, wihb + 256 * 64, tid); cpa_commit();  // G3 = wih2

    // s4: accB += whh0 @ x -> r; fold into n path
    cpa_wait1(); __syncthreads();
    gemm64(Ax, Wb0, accB, wm, wn, g, t4);
#pragma unroll
    for (int j = 0; j < 8; j++)
#pragma unroll
        for (int r = 0; r < 4; r++) {
            int col = wn * 64 + j * 8 + 2 * t4 + (r & 1);
            float rv = sigm(accB[j][r] + bih[col] + bhh[col]);
            accA[j][r] = rv * (accA[j][r] + bhh[256 + col]);
        }
    __syncthreads();
    cpa_tile(Wb0, wihb + 128 * 64, tid); cpa_commit();  // G4 = wih1

    // s5: accA += wih2 @ agg  (n preact)
    cpa_wait1(); __syncthreads();
    gemm64(Aagg, Wb1, accA, wm, wn, g, t4);
    __syncthreads();
    cpa_tile(Wb1, whhb + 128 * 64, tid); cpa_commit();  // G5 = whh1

    // s6: accB = wih1 @ agg
    zero8(accB);
    cpa_wait1(); __syncthreads();
    gemm64(Aagg, Wb0, accB, wm, wn, g, t4);
    __syncthreads();
    cpa_tile(Wb0, g1b, tid); cpa_commit();         // G6 = gin w1

    // s7: accB += whh1 @ x -> z ; h epilogue -> Aagg (smem only)
    cpa_wait1(); __syncthreads();
    gemm64(Ax, Wb1, accB, wm, wn, g, t4);
    {
        int rl_lo = wm * 16 + g;
        int rl_hi = rl_lo + 8;
#pragma unroll
        for (int j = 0; j < 8; j++) {
            int col = wn * 64 + j * 8 + 2 * t4;
            unsigned xp0 = Ax[rl_lo * KSTRIDE + (col >> 1)];
            unsigned xp1 = Ax[rl_hi * KSTRIDE + (col >> 1)];
            float z0 = sigm(accB[j][0] + bih[128 + col] + bhh[128 + col]);
            float z1 = sigm(accB[j][1] + bih[128 + col + 1] + bhh[128 + col + 1]);
            float z2 = sigm(accB[j][2] + bih[128 + col] + bhh[128 + col]);
            float z3 = sigm(accB[j][3] + bih[128 + col + 1] + bhh[128 + col + 1]);
            float n0 = tanhf(accA[j][0] + bih[256 + col]);
            float n1 = tanhf(accA[j][1] + bih[256 + col + 1]);
            float n2 = tanhf(accA[j][2] + bih[256 + col]);
            float n3 = tanhf(accA[j][3] + bih[256 + col + 1]);
            Aagg[rl_lo * KSTRIDE + (col >> 1)] =
                pack_bf16((1.f - z0) * n0 + z0 * bf_lo(xp0), (1.f - z1) * n1 + z1 * bf_hi(xp0));
            Aagg[rl_hi * KSTRIDE + (col >> 1)] =
                pack_bf16((1.f - z2) * n2 + z2 * bf_lo(xp1), (1.f - z3) * n3 + z3 * bf_hi(xp1));
        }
    }
    __syncthreads();
    cpa_tile(Wb1, g2b, tid); cpa_commit();         // G7 = gin w2

    // s8: t1 = relu(h @ g1^T + b1) -> Ax
    zero8(accA);
    cpa_wait1(); __syncthreads();
    gemm64(Aagg, Wb0, accA, wm, wn, g, t4);
    {
        int rl = wm * 16 + g;
#pragma unroll
        for (int j = 0; j < 8; j++) {
            int col = wn * 64 + j * 8 + 2 * t4;
            Ax[rl * KSTRIDE + (col >> 1)] =
                pack_bf16(fmaxf(accA[j][0] + b1v[col], 0.f), fmaxf(accA[j][1] + b1v[col + 1], 0.f));
            Ax[(rl + 8) * KSTRIDE + (col >> 1)] =
                pack_bf16(fmaxf(accA[j][2] + b1v[col], 0.f), fmaxf(accA[j][3] + b1v[col + 1], 0.f));
        }
    }
    __syncthreads();
    cpa_tile(Wb0, hw1b, tid); cpa_commit();        // G8 = head w1

    // s9: x = relu(t1 @ g2^T + b2); rowsum; normalize; write xb; repack to Aagg; load W2s
    zero8(accA);
    cpa_wait1(); __syncthreads();
    gemm64(Ax, Wb1, accA, wm, wn, g, t4);
    {
        float s_lo = 0.f, s_hi = 0.f;
#pragma unroll
        for (int j = 0; j < 8; j++) {
            int col = wn * 64 + j * 8 + 2 * t4;
            accA[j][0] = fmaxf(accA[j][0] + b2v[col], 0.f);
            accA[j][1] = fmaxf(accA[j][1] + b2v[col + 1], 0.f);
            accA[j][2] = fmaxf(accA[j][2] + b2v[col], 0.f);
            accA[j][3] = fmaxf(accA[j][3] + b2v[col + 1], 0.f);
            s_lo += accA[j][0] * accA[j][0] + accA[j][1] * accA[j][1];
            s_hi += accA[j][2] * accA[j][2] + accA[j][3] * accA[j][3];
        }
        atomicAdd(&rowsum[wm * 16 + g], s_lo);
        atomicAdd(&rowsum[wm * 16 + 8 + g], s_hi);
    }
    __syncthreads();
    {
        int rl = wm * 16 + g;
        float inv_lo = rsqrtf(1.f + rowsum[rl]);
        float inv_hi = rsqrtf(1.f + rowsum[rl + 8]);
        int gm_lo = m0 + rl;
        int gm_hi = gm_lo + 8;
#pragma unroll
        for (int j = 0; j < 8; j++) {
            int col = wn * 64 + j * 8 + 2 * t4;
            unsigned p_lo = pack_bf16(accA[j][0] * inv_lo, accA[j][1] * inv_lo);
            unsigned p_hi = pack_bf16(accA[j][2] * inv_hi, accA[j][3] * inv_hi);
            Aagg[rl * KSTRIDE + (col >> 1)] = p_lo;
            Aagg[(rl + 8) * KSTRIDE + (col >> 1)] = p_hi;
            if (gm_lo < M) xb[(size_t)gm_lo * 64 + (col >> 1)] = p_lo;
            if (gm_hi < M) xb[(size_t)gm_hi * 64 + (col >> 1)] = p_hi;
        }
    }
    for (int idx = tid; idx < 24 * 32; idx += 256) {
        int row = idx >> 5, c = idx & 31;
        float4 v = make_float4(0.f, 0.f, 0.f, 0.f);
        if (row < C) v = *reinterpret_cast<const float4*>(w2 + (size_t)row * HDIM + c * 4);
        W2s[row * KSTRIDE + c * 2 + 0] = pack_bf16(v.x, v.y);
        W2s[row * KSTRIDE + c * 2 + 1] = pack_bf16(v.z, v.w);
    }
    __syncthreads();

    // s10: t2 = relu(x @ hw1^T + hb1) -> Ax
    zero8(accA);
    cpa_wait0(); __syncthreads();
    gemm64(Aagg, Wb0, accA, wm, wn, g, t4);
    {
        int rl = wm * 16 + g;
#pragma unroll
        for (int j = 0; j < 8; j++) {
            int col = wn * 64 + j * 8 + 2 * t4;
            Ax[rl * KSTRIDE + (col >> 1)] =
                pack_bf16(fmaxf(accA[j][0] + hb1[col], 0.f), fmaxf(accA[j][1] + hb1[col + 1], 0.f));
            Ax[(rl + 8) * KSTRIDE + (col >> 1)] =
                pack_bf16(fmaxf(accA[j][2] + hb1[col], 0.f), fmaxf(accA[j][3] + hb1[col + 1], 0.f));
        }
    }
    __syncthreads();

    // s11: head logits (wn==0 warps), softmax
    float hacc[3][4];
#pragma unroll
    for (int j = 0; j < 3; j++)
#pragma unroll
        for (int r = 0; r < 4; r++) hacc[j][r] = 0.f;
    if (wn == 0) {
#pragma unroll
        for (int ks = 0; ks < 8; ks++) {
            int kb = ks * 8;
            int rb = wm * 16;
            unsigned af[4];
            af[0] = Ax[(rb + g) * KSTRIDE + kb + t4];
            af[1] = Ax[(rb + 8 + g) * KSTRIDE + kb + t4];
            af[2] = Ax[(rb + g) * KSTRIDE + kb + t4 + 4];
            af[3] = Ax[(rb + 8 + g) * KSTRIDE + kb + t4 + 4];
            unsigned bfr[3][2];
#pragma unroll
            for (int j = 0; j < 3; j++) {
                int nb = j * 8;
                bfr[j][0] = W2s[(nb + g) * KSTRIDE + kb + t4];
                bfr[j][1] = W2s[(nb + g) * KSTRIDE + kb + t4 + 4];
            }
#pragma unroll
            for (int j = 0; j < 3; j++)
                mma_bf16(hacc[j], af, bfr[j]);
        }
    }
    __syncthreads();
    float* logitp = reinterpret_cast<float*>(Ax);   // [64][28]
    if (wn == 0) {
        int rl = wm * 16 + g;
#pragma unroll
        for (int j = 0; j < 3; j++) {
            int col = j * 8 + 2 * t4;
            logitp[rl * 28 + col] = hacc[j][0];
            logitp[rl * 28 + col + 1] = hacc[j][1];
            logitp[(rl + 8) * 28 + col] = hacc[j][2];
            logitp[(rl + 8) * 28 + col + 1] = hacc[j][3];
        }
    }
    __syncthreads();

#pragma unroll
    for (int k = 0; k < 8; k++) {
        int nl = wid * 8 + k;
        int gm = m0 + nl;
        float myval = (lane < C) ? (logitp[nl * 28 + lane] + bh2[lane]) : 0.f;
        float mx = (lane < C) ? myval : -INFINITY;
#pragma unroll
        for (int o = 16; o; o >>= 1) mx = fmaxf(mx, __shfl_xor_sync(0xffffffffu, mx, o));
        float e = (lane < C) ? expf(myval - mx) : 0.f;
        float s = e;
#pragma unroll
        for (int o = 16; o; o >>= 1) s += __shfl_xor_sync(0xffffffffu, s, o);
        if (gm < M && lane < C) {
            olog [(size_t)gm * C + lane] = myval - mx - logf(s);
            osoft[(size_t)gm * C + lane] = e / s;
        }
    }
}
#define LAYER_SMEM ((2 * HTILE_U32 + 2 * TILE_U32 + 24 * KSTRIDE + 64) * 4)

// ---------------- launch ----------------
extern "C" void kernel_launch(void* const* d_in, const int* in_sizes, int n_in,
                              void* d_out, int out_size) {
    const float* features = (const float*)d_in[0];
    const int*   eidx     = (const int*)  d_in[1];
    const float* ew       = (const float*)d_in[2];
    const float* w1       = (const float*)d_in[3];
    const float* b1       = (const float*)d_in[4];
    const float* gin_w1   = (const float*)d_in[5];
    const float* gin_b1   = (const float*)d_in[6];
    const float* gin_w2   = (const float*)d_in[7];
    const float* gin_b2   = (const float*)d_in[8];
    const float* gru_wih  = (const float*)d_in[9];
    const float* gru_whh  = (const float*)d_in[10];
    const float* gru_bih  = (const float*)d_in[11];
    const float* gru_bhh  = (const float*)d_in[12];
    const float* head_w1  = (const float*)d_in[13];
    const float* head_b1  = (const float*)d_in[14];
    const float* hw2_0    = (const float*)d_in[15];
    const float* hb2_0    = (const float*)d_in[16];
    const float* hw2_1    = (const float*)d_in[17];
    const float* hb2_1    = (const float*)d_in[18];
    const float* hw2_2    = (const float*)d_in[19];
    const float* hb2_2    = (const float*)d_in[20];

    float* out = (float*)d_out;

    unsigned *p_xb, *p_aggb, *p_wb;
    int2 *p_csr_e;
    int *p_rowptr, *p_cursor, *p_bsum, *p_boff;
    cudaGetSymbolAddress((void**)&p_xb,     g_xb);
    cudaGetSymbolAddress((void**)&p_aggb,   g_aggb);
    cudaGetSymbolAddress((void**)&p_wb,     g_wb);
    cudaGetSymbolAddress((void**)&p_rowptr, g_rowptr);
    cudaGetSymbolAddress((void**)&p_cursor, g_cursor);
    cudaGetSymbolAddress((void**)&p_bsum,   g_blocksum);
    cudaGetSymbolAddress((void**)&p_boff,   g_blockoff);
    cudaGetSymbolAddress((void**)&p_csr_e,  g_csr_e);

    cudaFuncSetAttribute(k_gemm_mlp1,  cudaFuncAttributeMaxDynamicSharedMemorySize, GEMM_SMEM);
    cudaFuncSetAttribute(k_layer<2>,   cudaFuncAttributeMaxDynamicSharedMemorySize, LAYER_SMEM);
    cudaFuncSetAttribute(k_layer<6>,   cudaFuncAttributeMaxDynamicSharedMemorySize, LAYER_SMEM);
    cudaFuncSetAttribute(k_layer<21>,  cudaFuncAttributeMaxDynamicSharedMemorySize, LAYER_SMEM);

    const int M = NNODES;
    const int E = NEDGES;
    const int tile_gx   = (M + 127) / 128;   // 782
    const int tile64_gx = (M + 63) / 64;     // 1563
    const int warp_blocks = (M * 32 + 255) / 256;
    const int edge_blocks = (E + 255) / 256;
    const int node_blocks = (M + 255) / 256;

    const int* e_dst = eidx;
    const int* e_src = eidx + E;

    const size_t o_log0 = 0;
    const size_t o_log1 = (size_t)M * 2;
    const size_t o_log2 = (size_t)M * 8;
    const size_t o_soft = (size_t)M * 29;

    // ---- fused setup: pack weights + zero degree ----
    k_setup<<<(SETUP_TOTAL + 255) / 256, 256>>>(
        (const float4*)gru_wih, (const float4*)gru_whh,
        (const float4*)gin_w1, (const float4*)gin_w2, (const float4*)head_w1,
        (uint2*)p_wb, p_cursor);

    // ---- build CSR ----
    k_hist<<<edge_blocks, 256>>>(e_dst, p_cursor, E);
    k_scan_local<<<NSCANB, SCAN_B>>>(p_cursor, p_rowptr, p_bsum, M);
    k_scan_block2<<<1, 256>>>(p_bsum, p_boff, p_rowptr, NSCANB, M);
    k_scan_add<<<node_blocks, 256>>>(p_rowptr, p_cursor, p_boff, M);
    k_scatter<<<edge_blocks, 256>>>(e_dst, e_src, ew, p_cursor, p_csr_e, E);

    // x = relu(features @ w1^T + b1)  (bf16)
    k_gemm_mlp1<<<tile_gx, 256, GEMM_SMEM>>>(features, w1, b1, p_xb, M);

    for (int i = 0; i < NL; i++) {
        k_spmm_b<<<warp_blocks, 256>>>(p_rowptr, p_csr_e, p_xb, p_aggb, M);

        const unsigned* wihb = p_wb + OFF_WIH + (size_t)i * 384 * 64;
        const unsigned* whhb = p_wb + OFF_WHH + (size_t)i * 384 * 64;
        const unsigned* g1b  = p_wb + OFF_GW1 + (size_t)i * 128 * 64;
        const unsigned* g2b  = p_wb + OFF_GW2 + (size_t)i * 128 * 64;
        const unsigned* hw1b = p_wb + OFF_HW1 + (size_t)i * 128 * 64;
        const float* bih = gru_bih + (size_t)i * 384;
        const float* bhh = gru_bhh + (size_t)i * 384;

        if (i == 0)
            k_layer<2><<<tile64_gx, 256, LAYER_SMEM>>>(
                p_aggb, p_xb, wihb, whhb, bih, bhh,
                g1b, gin_b1, g2b, gin_b2, hw1b, head_b1, hw2_0, hb2_0,
                out + o_log0, out + o_soft, M);
        else if (i == 1)
            k_layer<6><<<tile64_gx, 256, LAYER_SMEM>>>(
                p_aggb, p_xb, wihb, whhb, bih, bhh,
                g1b, gin_b1 + HDIM, g2b, gin_b2 + HDIM,
                hw1b, head_b1 + HDIM, hw2_1, hb2_1,
                out + o_log1, out + o_soft + (size_t)M * 2, M);
        else
            k_layer<21><<<tile64_gx, 256, LAYER_SMEM>>>(
                p_aggb, p_xb, wihb, whhb, bih, bhh,
                g1b, gin_b1 + 2 * HDIM, g2b, gin_b2 + 2 * HDIM,
                hw1b, head_b1 + 2 * HDIM, hw2_2, hb2_2,
                out + o_log2, out + o_soft + (size_t)M * 8, M);
    }
}

// round 14
// speedup vs baseline: 1.6411x; 1.0226x over previous
#include <cuda_runtime.h>
#include <cuda_bf16.h>
#include <math.h>

#define NNODES 100000
#define NEDGES 1600000
#define HDIM   128
#define NL     3
#define SCAN_B 512
#define NSCANB ((NNODES + SCAN_B - 1) / SCAN_B)   // 196

#define KSTRIDE 68                 // smem row stride in u32 (64 bf16-pairs + pad 4)
#define TILE_U32 (128 * KSTRIDE)   // 128-row bf16 tile in u32
#define HTILE_U32 (64 * KSTRIDE)   // 64-row bf16 tile in u32

// prepacked bf16 weight buffer offsets (u32 units)
#define OFF_WIH 0
#define OFF_WHH (OFF_WIH + 3 * 384 * 64)
#define OFF_GW1 (OFF_WHH + 3 * 384 * 64)
#define OFF_GW2 (OFF_GW1 + 3 * 128 * 64)
#define OFF_HW1 (OFF_GW2 + 3 * 128 * 64)
#define WB_TOTAL (OFF_HW1 + 3 * 128 * 64)

// pack segment sizes in float4 units
#define N4_GRU (3 * 384 * HDIM / 4)   // 36864
#define N4_GIN (3 * HDIM * HDIM / 4)  // 12288
#define SETUP_TOTAL (2 * N4_GRU + 3 * N4_GIN + NNODES)

// ---------------- scratch (no allocations allowed) ----------------
__device__ unsigned g_xb  [(size_t)NNODES * 64];        // bf16 x
__device__ unsigned g_aggb[(size_t)NNODES * 64];        // bf16 agg
__device__ unsigned g_wb  [WB_TOTAL];                   // prepacked weights
// CSR scratch
__device__ int   g_rowptr[NNODES + 1];
__device__ int   g_cursor[NNODES];
__device__ int   g_blocksum[NSCANB];
__device__ int   g_blockoff[NSCANB];
__device__ int2  g_csr_e[NEDGES];                       // {src, w_bits}

// ---------------- helpers ----------------
__device__ __forceinline__ unsigned pack_bf16(float a, float b) {
    __nv_bfloat162 t = __floats2bfloat162_rn(a, b);
    return *reinterpret_cast<unsigned*>(&t);
}

__device__ __forceinline__ void mma_bf16(float* d, const unsigned* a, const unsigned* b) {
    asm volatile(
        "mma.sync.aligned.m16n8k16.row.col.f32.bf16.bf16.f32 "
        "{%0,%1,%2,%3}, {%4,%5,%6,%7}, {%8,%9}, {%0,%1,%2,%3};\n"
        : "+f"(d[0]), "+f"(d[1]), "+f"(d[2]), "+f"(d[3])
        : "r"(a[0]), "r"(a[1]), "r"(a[2]), "r"(a[3]), "r"(b[0]), "r"(b[1]));
}

__device__ __forceinline__ void ldsm_x4(unsigned& r0, unsigned& r1, unsigned& r2, unsigned& r3,
                                        const unsigned* p) {
    unsigned addr = (unsigned)__cvta_generic_to_shared(p);
    asm volatile("ldmatrix.sync.aligned.m8n8.x4.shared.b16 {%0,%1,%2,%3}, [%4];"
                 : "=r"(r0), "=r"(r1), "=r"(r2), "=r"(r3) : "r"(addr));
}

__device__ __forceinline__ void cpa16(unsigned* smem_dst, const unsigned* g, bool valid) {
    unsigned saddr = (unsigned)__cvta_generic_to_shared(smem_dst);
    int sz = valid ? 16 : 0;
    asm volatile("cp.async.cg.shared.global [%0], [%1], 16, %2;\n"
                 :: "r"(saddr), "l"(g), "r"(sz) : "memory");
}
__device__ __forceinline__ void cpa_commit() {
    asm volatile("cp.async.commit_group;\n" ::: "memory");
}
__device__ __forceinline__ void cpa_wait0() {
    asm volatile("cp.async.wait_group 0;\n" ::: "memory");
}
__device__ __forceinline__ void cpa_wait1() {
    asm volatile("cp.async.wait_group 1;\n" ::: "memory");
}

// 128-row tile async copy (weights)
__device__ __forceinline__ void cpa_tile(unsigned* dst, const unsigned* __restrict__ src,
                                         int tid) {
#pragma unroll
    for (int p = 0; p < 8; p++) {
        int F = p * 256 + tid;
        int row = F >> 4;
        int c4 = (F & 15) * 4;
        cpa16(dst + row * KSTRIDE + c4, src + (size_t)row * 64 + c4, true);
    }
}

// 64-row tile async copy (activations), OOB rows zero-filled
__device__ __forceinline__ void cpa_tile64(unsigned* dst, const unsigned* __restrict__ src,
                                           int row0, int Mrows, int tid) {
#pragma unroll
    for (int p = 0; p < 4; p++) {
        int F = p * 256 + tid;
        int row = F >> 4;
        int c4 = (F & 15) * 4;
        bool v = (row0 + row) < Mrows;
        cpa16(dst + row * KSTRIDE + c4, src + (size_t)(row0 + row) * 64 + c4, v);
    }
}

// acc += A64 @ W128^T for this warp (64-row A tile) — ldmatrix fragment loads
__device__ __forceinline__ void gemm64(const unsigned* __restrict__ As,
                                       const unsigned* __restrict__ Ws,
                                       float acc[8][4],
                                       int wm, int wn, int lane) {
    const int li = lane >> 3;          // matrix id 0..3
    const int lr = lane & 7;           // row within matrix
    // A: row = wm*16 + (li&1)*8 + lr ; k-pair offset = (li>>1)*4
    const unsigned* abase = As + (wm * 16 + (li & 1) * 8 + lr) * KSTRIDE + (li >> 1) * 4;
    // B: nrow = wn*64 + jp*16 + (li>>1)*8 + lr ; k-pair offset = (li&1)*4
    const unsigned* bbase = Ws + (wn * 64 + (li >> 1) * 8 + lr) * KSTRIDE + (li & 1) * 4;
#pragma unroll
    for (int ks = 0; ks < 8; ks++) {
        int kb = ks * 8;
        unsigned af[4];
        ldsm_x4(af[0], af[1], af[2], af[3], abase + kb);
#pragma unroll
        for (int jp = 0; jp < 4; jp++) {
            unsigned b0, b1, b2, b3;
            ldsm_x4(b0, b1, b2, b3, bbase + jp * 16 * KSTRIDE + kb);
            unsigned blo[2] = {b0, b1};
            unsigned bhi[2] = {b2, b3};
            mma_bf16(acc[2 * jp], af, blo);
            mma_bf16(acc[2 * jp + 1], af, bhi);
        }
    }
}

// 128-row variant (mlp1) — unchanged scalar-LDS version
__device__ __forceinline__ void gemm128(const unsigned* __restrict__ As,
                                        const unsigned* __restrict__ Ws,
                                        float acc[2][8][4],
                                        int wm, int wn, int g, int t4) {
#pragma unroll
    for (int ks = 0; ks < 8; ks++) {
        int kb = ks * 8;
        unsigned af[2][4];
#pragma unroll
        for (int i = 0; i < 2; i++) {
            int rb = wm * 32 + i * 16;
            af[i][0] = As[(rb + g) * KSTRIDE + kb + t4];
            af[i][1] = As[(rb + 8 + g) * KSTRIDE + kb + t4];
            af[i][2] = As[(rb + g) * KSTRIDE + kb + t4 + 4];
            af[i][3] = As[(rb + 8 + g) * KSTRIDE + kb + t4 + 4];
        }
        unsigned bf[8][2];
#pragma unroll
        for (int j = 0; j < 8; j++) {
            int nb = wn * 64 + j * 8;
            bf[j][0] = Ws[(nb + g) * KSTRIDE + kb + t4];
            bf[j][1] = Ws[(nb + g) * KSTRIDE + kb + t4 + 4];
        }
#pragma unroll
        for (int i = 0; i < 2; i++)
#pragma unroll
            for (int j = 0; j < 8; j++)
                mma_bf16(acc[i][j], af[i], bf[j]);
    }
}

__device__ __forceinline__ void zero8(float acc[8][4]) {
#pragma unroll
    for (int j = 0; j < 8; j++)
#pragma unroll
        for (int r = 0; r < 4; r++) acc[j][r] = 0.f;
}

// load 128x128 f32 tile -> bf16 smem (mlp1 features / weights)
__device__ __forceinline__ void load_tile_g(unsigned* dst, const float* __restrict__ src,
                                            int row0, int M, int tid) {
#pragma unroll
    for (int p = 0; p < 16; p++) {
        int F = p * 256 + tid;
        int row = F >> 5, c = F & 31;
        float4 v = make_float4(0.f, 0.f, 0.f, 0.f);
        if (row0 + row < M) v = *reinterpret_cast<const float4*>(src + (size_t)(row0 + row) * HDIM + c * 4);
        dst[row * KSTRIDE + c * 2 + 0] = pack_bf16(v.x, v.y);
        dst[row * KSTRIDE + c * 2 + 1] = pack_bf16(v.z, v.w);
    }
}

__device__ __forceinline__ float sigm(float x) { return 1.f / (1.f + expf(-x)); }
__device__ __forceinline__ float bf_lo(unsigned p) { return __uint_as_float(p << 16); }
__device__ __forceinline__ float bf_hi(unsigned p) { return __uint_as_float(p & 0xffff0000u); }

// ---------------- fused setup: pack all weights + zero degree counters ----------------
__global__ void k_setup(const float4* __restrict__ wih, const float4* __restrict__ whh,
                        const float4* __restrict__ gw1, const float4* __restrict__ gw2,
                        const float4* __restrict__ hw1,
                        uint2* __restrict__ wb, int* __restrict__ deg) {
    int i = blockIdx.x * blockDim.x + threadIdx.x;
    if (i >= SETUP_TOTAL) return;
    const float4* src;
    uint2* dst;
    int idx = i;
    if (idx < N4_GRU) { src = wih; dst = wb + OFF_WIH / 2; }
    else if ((idx -= N4_GRU) < N4_GRU) { src = whh; dst = wb + OFF_WHH / 2; }
    else if ((idx -= N4_GRU) < N4_GIN) { src = gw1; dst = wb + OFF_GW1 / 2; }
    else if ((idx -= N4_GIN) < N4_GIN) { src = gw2; dst = wb + OFF_GW2 / 2; }
    else if ((idx -= N4_GIN) < N4_GIN) { src = hw1; dst = wb + OFF_HW1 / 2; }
    else { deg[idx - N4_GIN] = 0; return; }
    float4 v = src[idx];
    dst[idx] = make_uint2(pack_bf16(v.x, v.y), pack_bf16(v.z, v.w));
}

// ---------------- CSR build ----------------
__global__ void k_hist(const int* __restrict__ dst, int* __restrict__ deg, int E) {
    int i = blockIdx.x * blockDim.x + threadIdx.x;
    if (i < E) atomicAdd(&deg[dst[i]], 1);
}

__global__ __launch_bounds__(SCAN_B) void k_scan_local(const int* __restrict__ deg,
                                                       int* __restrict__ rowptr,
                                                       int* __restrict__ blocksum, int n) {
    __shared__ int s[SCAN_B];
    int tid = threadIdx.x;
    int i = blockIdx.x * SCAN_B + tid;
    int v = (i < n) ? deg[i] : 0;
    s[tid] = v;
    __syncthreads();
    for (int off = 1; off < SCAN_B; off <<= 1) {
        int t = (tid >= off) ? s[tid - off] : 0;
        __syncthreads();
        s[tid] += t;
        __syncthreads();
    }
    if (i < n) rowptr[i] = s[tid] - v;
    if (tid == SCAN_B - 1) blocksum[blockIdx.x] = s[tid];
}

__global__ __launch_bounds__(256) void k_scan_block2(const int* __restrict__ blocksum,
                                                     int* __restrict__ blockoff,
                                                     int* __restrict__ rowptr, int nblk, int n) {
    __shared__ int s[256];
    int tid = threadIdx.x;
    int v = (tid < nblk) ? blocksum[tid] : 0;
    s[tid] = v;
    __syncthreads();
    for (int off = 1; off < 256; off <<= 1) {
        int t = (tid >= off) ? s[tid - off] : 0;
        __syncthreads();
        s[tid] += t;
        __syncthreads();
    }
    if (tid < nblk) blockoff[tid] = s[tid] - v;
    if (tid == 255) rowptr[n] = s[255];
}

__global__ void k_scan_add(int* __restrict__ rowptr, int* __restrict__ cursor,
                           const int* __restrict__ blockoff, int n) {
    int i = blockIdx.x * blockDim.x + threadIdx.x;
    if (i < n) {
        int v = rowptr[i] + blockoff[i / SCAN_B];
        rowptr[i] = v;
        cursor[i] = v;
    }
}

__global__ void k_scatter(const int* __restrict__ dst, const int* __restrict__ src,
                          const float* __restrict__ ew, int* __restrict__ cursor,
                          int2* __restrict__ csr_e, int E) {
    int i = blockIdx.x * blockDim.x + threadIdx.x;
    if (i < E) {
        int pos = atomicAdd(&cursor[dst[i]], 1);
        csr_e[pos] = make_int2(src[i], __float_as_int(ew[i]));
    }
}

// ---------------- SpMM (CSR, warp per node, int4 edge-pair loads) ----------------
__global__ __launch_bounds__(256) void k_spmm_b(
    const int* __restrict__ rowptr, const int2* __restrict__ csr_e,
    const unsigned* __restrict__ xb, unsigned* __restrict__ aggb, int n) {
    int row = (blockIdx.x * blockDim.x + threadIdx.x) >> 5;
    int lane = threadIdx.x & 31;
    if (row >= n) return;
    int e = rowptr[row];
    int end = rowptr[row + 1];
    const uint2* x2 = reinterpret_cast<const uint2*>(xb);
    float a0 = 0.f, a1 = 0.f, a2 = 0.f, a3 = 0.f;
    if ((e & 1) && e < end) {
        int2 E0 = csr_e[e];
        float w0 = __int_as_float(E0.y);
        uint2 v0 = x2[(size_t)E0.x * 32 + lane];
        a0 = fmaf(w0, bf_lo(v0.x), a0); a1 = fmaf(w0, bf_hi(v0.x), a1);
        a2 = fmaf(w0, bf_lo(v0.y), a2); a3 = fmaf(w0, bf_hi(v0.y), a3);
        e++;
    }
    const int4* e2 = reinterpret_cast<const int4*>(csr_e);
    int np = (end - e) >> 1;
    int p = e >> 1;
    for (; np >= 2; np -= 2, p += 2) {
        int4 P0 = e2[p];
        int4 P1 = e2[p + 1];
        uint2 v0 = x2[(size_t)P0.x * 32 + lane];
        uint2 v1 = x2[(size_t)P0.z * 32 + lane];
        uint2 v2 = x2[(size_t)P1.x * 32 + lane];
        uint2 v3 = x2[(size_t)P1.z * 32 + lane];
        float w0 = __int_as_float(P0.y), w1 = __int_as_float(P0.w);
        float w2 = __int_as_float(P1.y), w3 = __int_as_float(P1.w);
        a0 = fmaf(w0, bf_lo(v0.x), a0); a1 = fmaf(w0, bf_hi(v0.x), a1);
        a2 = fmaf(w0, bf_lo(v0.y), a2); a3 = fmaf(w0, bf_hi(v0.y), a3);
        a0 = fmaf(w1, bf_lo(v1.x), a0); a1 = fmaf(w1, bf_hi(v1.x), a1);
        a2 = fmaf(w1, bf_lo(v1.y), a2); a3 = fmaf(w1, bf_hi(v1.y), a3);
        a0 = fmaf(w2, bf_lo(v2.x), a0); a1 = fmaf(w2, bf_hi(v2.x), a1);
        a2 = fmaf(w2, bf_lo(v2.y), a2); a3 = fmaf(w2, bf_hi(v2.y), a3);
        a0 = fmaf(w3, bf_lo(v3.x), a0); a1 = fmaf(w3, bf_hi(v3.x), a1);
        a2 = fmaf(w3, bf_lo(v3.y), a2); a3 = fmaf(w3, bf_hi(v3.y), a3);
    }
    if (np) {
        int4 P0 = e2[p];
        uint2 v0 = x2[(size_t)P0.x * 32 + lane];
        uint2 v1 = x2[(size_t)P0.z * 32 + lane];
        float w0 = __int_as_float(P0.y), w1 = __int_as_float(P0.w);
        a0 = fmaf(w0, bf_lo(v0.x), a0); a1 = fmaf(w0, bf_hi(v0.x), a1);
        a2 = fmaf(w0, bf_lo(v0.y), a2); a3 = fmaf(w0, bf_hi(v0.y), a3);
        a0 = fmaf(w1, bf_lo(v1.x), a0); a1 = fmaf(w1, bf_hi(v1.x), a1);
        a2 = fmaf(w1, bf_lo(v1.y), a2); a3 = fmaf(w1, bf_hi(v1.y), a3);
    }
    if ((end - e) & 1) {
        int2 E0 = csr_e[end - 1];
        float w0 = __int_as_float(E0.y);
        uint2 v0 = x2[(size_t)E0.x * 32 + lane];
        a0 = fmaf(w0, bf_lo(v0.x), a0); a1 = fmaf(w0, bf_hi(v0.x), a1);
        a2 = fmaf(w0, bf_lo(v0.y), a2); a3 = fmaf(w0, bf_hi(v0.y), a3);
    }
    *reinterpret_cast<uint2*>(aggb + (size_t)row * 64 + lane * 2) =
        make_uint2(pack_bf16(a0, a1), pack_bf16(a2, a3));
}

// ---------------- mlp1 GEMM: xb = bf16(relu(features @ w1^T + b1)) ----------------
__global__ __launch_bounds__(256) void k_gemm_mlp1(
    const float* __restrict__ A, const float* __restrict__ W,
    const float* __restrict__ bias, unsigned* __restrict__ Cb, int M)
{
    extern __shared__ unsigned smem_u[];
    unsigned* As = smem_u;
    unsigned* Ws = smem_u + TILE_U32;

    const int tid = threadIdx.x;
    const int wid = tid >> 5;
    const int lane = tid & 31;
    const int g = lane >> 2;
    const int t4 = lane & 3;
    const int wm = wid & 3;
    const int wn = wid >> 2;
    const int m0 = blockIdx.x * 128;

    load_tile_g(As, A, m0, M, tid);
#pragma unroll
    for (int p = 0; p < 16; p++) {
        int F = p * 256 + tid;
        int row = F >> 5, c = F & 31;
        float4 v = *reinterpret_cast<const float4*>(W + (size_t)row * HDIM + c * 4);
        Ws[row * KSTRIDE + c * 2 + 0] = pack_bf16(v.x, v.y);
        Ws[row * KSTRIDE + c * 2 + 1] = pack_bf16(v.z, v.w);
    }
    __syncthreads();

    float acc[2][8][4];
#pragma unroll
    for (int i = 0; i < 2; i++) zero8(acc[i]);
    gemm128(As, Ws, acc, wm, wn, g, t4);

#pragma unroll
    for (int i = 0; i < 2; i++) {
        int row_lo = m0 + wm * 32 + i * 16 + g;
        int row_hi = row_lo + 8;
#pragma unroll
        for (int j = 0; j < 8; j++) {
            int col = wn * 64 + j * 8 + 2 * t4;
            float b0 = bias[col];
            float b1 = bias[col + 1];
            if (row_lo < M)
                Cb[(size_t)row_lo * 64 + (col >> 1)] =
                    pack_bf16(fmaxf(acc[i][j][0] + b0, 0.f), fmaxf(acc[i][j][1] + b1, 0.f));
            if (row_hi < M)
                Cb[(size_t)row_hi * 64 + (col >> 1)] =
                    pack_bf16(fmaxf(acc[i][j][2] + b0, 0.f), fmaxf(acc[i][j][3] + b1, 0.f));
        }
    }
}
#define GEMM_SMEM (2 * TILE_U32 * 4)

// ---------------- fused LAYER: GRU + GIN MLP + norm + head + softmax ----------------
template <int C>
__global__ __launch_bounds__(256, 2) void k_layer(
    const unsigned* __restrict__ aggb, unsigned* xb,
    const unsigned* __restrict__ wihb, const unsigned* __restrict__ whhb,
    const float* __restrict__ bih, const float* __restrict__ bhh,
    const unsigned* __restrict__ g1b, const float* __restrict__ b1v,
    const unsigned* __restrict__ g2b, const float* __restrict__ b2v,
    const unsigned* __restrict__ hw1b, const float* __restrict__ hb1,
    const float* __restrict__ w2, const float* __restrict__ bh2,
    float* __restrict__ olog, float* __restrict__ osoft, int M)
{
    extern __shared__ unsigned sm[];
    unsigned* Aagg = sm;                          // agg tile -> h tile -> x tile
    unsigned* Ax   = sm + HTILE_U32;              // x tile -> t1/t2/logits
    unsigned* Wb0  = sm + 2 * HTILE_U32;
    unsigned* Wb1  = Wb0 + TILE_U32;
    unsigned* W2s  = Wb1 + TILE_U32;              // head w2 (24 rows)
    float* rowsum  = reinterpret_cast<float*>(W2s + 24 * KSTRIDE);  // [64]

    const int tid = threadIdx.x;
    const int wid = tid >> 5;
    const int lane = tid & 31;
    const int g = lane >> 2;
    const int t4 = lane & 3;
    const int wm = wid & 3;
    const int wn = wid >> 2;
    const int m0 = blockIdx.x * 64;

    if (tid < 64) rowsum[tid] = 0.f;

    cpa_tile64(Aagg, aggb, m0, M, tid);
    cpa_tile64(Ax,   xb,   m0, M, tid);
    cpa_tile(Wb0, whhb + 256 * 64, tid);
    cpa_commit();                                  // G0
    cpa_tile(Wb1, wihb, tid);
    cpa_commit();                                  // G1

    float accA[8][4], accB[8][4];
    zero8(accA); zero8(accB);

    // s2: accA = whh2 @ x
    cpa_wait1(); __syncthreads();
    gemm64(Ax, Wb0, accA, wm, wn, lane);
    __syncthreads();
    cpa_tile(Wb0, whhb, tid); cpa_commit();        // G2 = whh0

    // s3: accB = wih0 @ agg
    cpa_wait1(); __syncthreads();
    gemm64(Aagg, Wb1, accB, wm, wn, lane);
    __syncthreads();
    cpa_tile(Wb1, wihb + 256 * 64, tid); cpa_commit();  // G3 = wih2

    // s4: accB += whh0 @ x -> r; fold into n path
    cpa_wait1(); __syncthreads();
    gemm64(Ax, Wb0, accB, wm, wn, lane);
#pragma unroll
    for (int j = 0; j < 8; j++)
#pragma unroll
        for (int r = 0; r < 4; r++) {
            int col = wn * 64 + j * 8 + 2 * t4 + (r & 1);
            float rv = sigm(accB[j][r] + bih[col] + bhh[col]);
            accA[j][r] = rv * (accA[j][r] + bhh[256 + col]);
        }
    __syncthreads();
    cpa_tile(Wb0, wihb + 128 * 64, tid); cpa_commit();  // G4 = wih1

    // s5: accA += wih2 @ agg  (n preact)
    cpa_wait1(); __syncthreads();
    gemm64(Aagg, Wb1, accA, wm, wn, lane);
    __syncthreads();
    cpa_tile(Wb1, whhb + 128 * 64, tid); cpa_commit();  // G5 = whh1

    // s6: accB = wih1 @ agg
    zero8(accB);
    cpa_wait1(); __syncthreads();
    gemm64(Aagg, Wb0, accB, wm, wn, lane);
    __syncthreads();
    cpa_tile(Wb0, g1b, tid); cpa_commit();         // G6 = gin w1

    // s7: accB += whh1 @ x -> z ; h epilogue -> Aagg (smem only)
    cpa_wait1(); __syncthreads();
    gemm64(Ax, Wb1, accB, wm, wn, lane);
    {
        int rl_lo = wm * 16 + g;
        int rl_hi = rl_lo + 8;
#pragma unroll
        for (int j = 0; j < 8; j++) {
            int col = wn * 64 + j * 8 + 2 * t4;
            unsigned xp0 = Ax[rl_lo * KSTRIDE + (col >> 1)];
            unsigned xp1 = Ax[rl_hi * KSTRIDE + (col >> 1)];
            float z0 = sigm(accB[j][0] + bih[128 + col] + bhh[128 + col]);
            float z1 = sigm(accB[j][1] + bih[128 + col + 1] + bhh[128 + col + 1]);
            float z2 = sigm(accB[j][2] + bih[128 + col] + bhh[128 + col]);
            float z3 = sigm(accB[j][3] + bih[128 + col + 1] + bhh[128 + col + 1]);
            float n0 = tanhf(accA[j][0] + bih[256 + col]);
            float n1 = tanhf(accA[j][1] + bih[256 + col + 1]);
            float n2 = tanhf(accA[j][2] + bih[256 + col]);
            float n3 = tanhf(accA[j][3] + bih[256 + col + 1]);
            Aagg[rl_lo * KSTRIDE + (col >> 1)] =
                pack_bf16((1.f - z0) * n0 + z0 * bf_lo(xp0), (1.f - z1) * n1 + z1 * bf_hi(xp0));
            Aagg[rl_hi * KSTRIDE + (col >> 1)] =
                pack_bf16((1.f - z2) * n2 + z2 * bf_lo(xp1), (1.f - z3) * n3 + z3 * bf_hi(xp1));
        }
    }
    __syncthreads();
    cpa_tile(Wb1, g2b, tid); cpa_commit();         // G7 = gin w2

    // s8: t1 = relu(h @ g1^T + b1) -> Ax
    zero8(accA);
    cpa_wait1(); __syncthreads();
    gemm64(Aagg, Wb0, accA, wm, wn, lane);
    {
        int rl = wm * 16 + g;
#pragma unroll
        for (int j = 0; j < 8; j++) {
            int col = wn * 64 + j * 8 + 2 * t4;
            Ax[rl * KSTRIDE + (col >> 1)] =
                pack_bf16(fmaxf(accA[j][0] + b1v[col], 0.f), fmaxf(accA[j][1] + b1v[col + 1], 0.f));
            Ax[(rl + 8) * KSTRIDE + (col >> 1)] =
                pack_bf16(fmaxf(accA[j][2] + b1v[col], 0.f), fmaxf(accA[j][3] + b1v[col + 1], 0.f));
        }
    }
    __syncthreads();
    cpa_tile(Wb0, hw1b, tid); cpa_commit();        // G8 = head w1

    // s9: x = relu(t1 @ g2^T + b2); rowsum; normalize; write xb; repack to Aagg; load W2s
    zero8(accA);
    cpa_wait1(); __syncthreads();
    gemm64(Ax, Wb1, accA, wm, wn, lane);
    {
        float s_lo = 0.f, s_hi = 0.f;
#pragma unroll
        for (int j = 0; j < 8; j++) {
            int col = wn * 64 + j * 8 + 2 * t4;
            accA[j][0] = fmaxf(accA[j][0] + b2v[col], 0.f);
            accA[j][1] = fmaxf(accA[j][1] + b2v[col + 1], 0.f);
            accA[j][2] = fmaxf(accA[j][2] + b2v[col], 0.f);
            accA[j][3] = fmaxf(accA[j][3] + b2v[col + 1], 0.f);
            s_lo += accA[j][0] * accA[j][0] + accA[j][1] * accA[j][1];
            s_hi += accA[j][2] * accA[j][2] + accA[j][3] * accA[j][3];
        }
        atomicAdd(&rowsum[wm * 16 + g], s_lo);
        atomicAdd(&rowsum[wm * 16 + 8 + g], s_hi);
    }
    __syncthreads();
    {
        int rl = wm * 16 + g;
        float inv_lo = rsqrtf(1.f + rowsum[rl]);
        float inv_hi = rsqrtf(1.f + rowsum[rl + 8]);
        int gm_lo = m0 + rl;
        int gm_hi = gm_lo + 8;
#pragma unroll
        for (int j = 0; j < 8; j++) {
            int col = wn * 64 + j * 8 + 2 * t4;
            unsigned p_lo = pack_bf16(accA[j][0] * inv_lo, accA[j][1] * inv_lo);
            unsigned p_hi = pack_bf16(accA[j][2] * inv_hi, accA[j][3] * inv_hi);
            Aagg[rl * KSTRIDE + (col >> 1)] = p_lo;
            Aagg[(rl + 8) * KSTRIDE + (col >> 1)] = p_hi;
            if (gm_lo < M) xb[(size_t)gm_lo * 64 + (col >> 1)] = p_lo;
            if (gm_hi < M) xb[(size_t)gm_hi * 64 + (col >> 1)] = p_hi;
        }
    }
    for (int idx = tid; idx < 24 * 32; idx += 256) {
        int row = idx >> 5, c = idx & 31;
        float4 v = make_float4(0.f, 0.f, 0.f, 0.f);
        if (row < C) v = *reinterpret_cast<const float4*>(w2 + (size_t)row * HDIM + c * 4);
        W2s[row * KSTRIDE + c * 2 + 0] = pack_bf16(v.x, v.y);
        W2s[row * KSTRIDE + c * 2 + 1] = pack_bf16(v.z, v.w);
    }
    __syncthreads();

    // s10: t2 = relu(x @ hw1^T + hb1) -> Ax
    zero8(accA);
    cpa_wait0(); __syncthreads();
    gemm64(Aagg, Wb0, accA, wm, wn, lane);
    {
        int rl = wm * 16 + g;
#pragma unroll
        for (int j = 0; j < 8; j++) {
            int col = wn * 64 + j * 8 + 2 * t4;
            Ax[rl * KSTRIDE + (col >> 1)] =
                pack_bf16(fmaxf(accA[j][0] + hb1[col], 0.f), fmaxf(accA[j][1] + hb1[col + 1], 0.f));
            Ax[(rl + 8) * KSTRIDE + (col >> 1)] =
                pack_bf16(fmaxf(accA[j][2] + hb1[col], 0.f), fmaxf(accA[j][3] + hb1[col + 1], 0.f));
        }
    }
    __syncthreads();

    // s11: head logits (wn==0 warps), softmax
    float hacc[3][4];
#pragma unroll
    for (int j = 0; j < 3; j++)
#pragma unroll
        for (int r = 0; r < 4; r++) hacc[j][r] = 0.f;
    if (wn == 0) {
#pragma unroll
        for (int ks = 0; ks < 8; ks++) {
            int kb = ks * 8;
            int rb = wm * 16;
            unsigned af[4];
            af[0] = Ax[(rb + g) * KSTRIDE + kb + t4];
            af[1] = Ax[(rb + 8 + g) * KSTRIDE + kb + t4];
            af[2] = Ax[(rb + g) * KSTRIDE + kb + t4 + 4];
            af[3] = Ax[(rb + 8 + g) * KSTRIDE + kb + t4 + 4];
            unsigned bfr[3][2];
#pragma unroll
            for (int j = 0; j < 3; j++) {
                int nb = j * 8;
                bfr[j][0] = W2s[(nb + g) * KSTRIDE + kb + t4];
                bfr[j][1] = W2s[(nb + g) * KSTRIDE + kb + t4 + 4];
            }
#pragma unroll
            for (int j = 0; j < 3; j++)
                mma_bf16(hacc[j], af, bfr[j]);
        }
    }
    __syncthreads();
    float* logitp = reinterpret_cast<float*>(Ax);   // [64][28]
    if (wn == 0) {
        int rl = wm * 16 + g;
#pragma unroll
        for (int j = 0; j < 3; j++) {
            int col = j * 8 + 2 * t4;
            logitp[rl * 28 + col] = hacc[j][0];
            logitp[rl * 28 + col + 1] = hacc[j][1];
            logitp[(rl + 8) * 28 + col] = hacc[j][2];
            logitp[(rl + 8) * 28 + col + 1] = hacc[j][3];
        }
    }
    __syncthreads();

#pragma unroll
    for (int k = 0; k < 8; k++) {
        int nl = wid * 8 + k;
        int gm = m0 + nl;
        float myval = (lane < C) ? (logitp[nl * 28 + lane] + bh2[lane]) : 0.f;
        float mx = (lane < C) ? myval : -INFINITY;
#pragma unroll
        for (int o = 16; o; o >>= 1) mx = fmaxf(mx, __shfl_xor_sync(0xffffffffu, mx, o));
        float e = (lane < C) ? expf(myval - mx) : 0.f;
        float s = e;
#pragma unroll
        for (int o = 16; o; o >>= 1) s += __shfl_xor_sync(0xffffffffu, s, o);
        if (gm < M && lane < C) {
            olog [(size_t)gm * C + lane] = myval - mx - logf(s);
            osoft[(size_t)gm * C + lane] = e / s;
        }
    }
}
#define LAYER_SMEM ((2 * HTILE_U32 + 2 * TILE_U32 + 24 * KSTRIDE + 64) * 4)

// ---------------- launch ----------------
extern "C" void kernel_launch(void* const* d_in, const int* in_sizes, int n_in,
                              void* d_out, int out_size) {
    const float* features = (const float*)d_in[0];
    const int*   eidx     = (const int*)  d_in[1];
    const float* ew       = (const float*)d_in[2];
    const float* w1       = (const float*)d_in[3];
    const float* b1       = (const float*)d_in[4];
    const float* gin_w1   = (const float*)d_in[5];
    const float* gin_b1   = (const float*)d_in[6];
    const float* gin_w2   = (const float*)d_in[7];
    const float* gin_b2   = (const float*)d_in[8];
    const float* gru_wih  = (const float*)d_in[9];
    const float* gru_whh  = (const float*)d_in[10];
    const float* gru_bih  = (const float*)d_in[11];
    const float* gru_bhh  = (const float*)d_in[12];
    const float* head_w1  = (const float*)d_in[13];
    const float* head_b1  = (const float*)d_in[14];
    const float* hw2_0    = (const float*)d_in[15];
    const float* hb2_0    = (const float*)d_in[16];
    const float* hw2_1    = (const float*)d_in[17];
    const float* hb2_1    = (const float*)d_in[18];
    const float* hw2_2    = (const float*)d_in[19];
    const float* hb2_2    = (const float*)d_in[20];

    float* out = (float*)d_out;

    unsigned *p_xb, *p_aggb, *p_wb;
    int2 *p_csr_e;
    int *p_rowptr, *p_cursor, *p_bsum, *p_boff;
    cudaGetSymbolAddress((void**)&p_xb,     g_xb);
    cudaGetSymbolAddress((void**)&p_aggb,   g_aggb);
    cudaGetSymbolAddress((void**)&p_wb,     g_wb);
    cudaGetSymbolAddress((void**)&p_rowptr, g_rowptr);
    cudaGetSymbolAddress((void**)&p_cursor, g_cursor);
    cudaGetSymbolAddress((void**)&p_bsum,   g_blocksum);
    cudaGetSymbolAddress((void**)&p_boff,   g_blockoff);
    cudaGetSymbolAddress((void**)&p_csr_e,  g_csr_e);

    cudaFuncSetAttribute(k_gemm_mlp1,  cudaFuncAttributeMaxDynamicSharedMemorySize, GEMM_SMEM);
    cudaFuncSetAttribute(k_layer<2>,   cudaFuncAttributeMaxDynamicSharedMemorySize, LAYER_SMEM);
    cudaFuncSetAttribute(k_layer<6>,   cudaFuncAttributeMaxDynamicSharedMemorySize, LAYER_SMEM);
    cudaFuncSetAttribute(k_layer<21>,  cudaFuncAttributeMaxDynamicSharedMemorySize, LAYER_SMEM);

    const int M = NNODES;
    const int E = NEDGES;
    const int tile_gx   = (M + 127) / 128;   // 782
    const int tile64_gx = (M + 63) / 64;     // 1563
    const int warp_blocks = (M * 32 + 255) / 256;
    const int edge_blocks = (E + 255) / 256;
    const int node_blocks = (M + 255) / 256;

    const int* e_dst = eidx;
    const int* e_src = eidx + E;

    const size_t o_log0 = 0;
    const size_t o_log1 = (size_t)M * 2;
    const size_t o_log2 = (size_t)M * 8;
    const size_t o_soft = (size_t)M * 29;

    // ---- fused setup: pack weights + zero degree ----
    k_setup<<<(SETUP_TOTAL + 255) / 256, 256>>>(
        (const float4*)gru_wih, (const float4*)gru_whh,
        (const float4*)gin_w1, (const float4*)gin_w2, (const float4*)head_w1,
        (uint2*)p_wb, p_cursor);

    // ---- build CSR ----
    k_hist<<<edge_blocks, 256>>>(e_dst, p_cursor, E);
    k_scan_local<<<NSCANB, SCAN_B>>>(p_cursor, p_rowptr, p_bsum, M);
    k_scan_block2<<<1, 256>>>(p_bsum, p_boff, p_rowptr, NSCANB, M);
    k_scan_add<<<node_blocks, 256>>>(p_rowptr, p_cursor, p_boff, M);
    k_scatter<<<edge_blocks, 256>>>(e_dst, e_src, ew, p_cursor, p_csr_e, E);

    // x = relu(features @ w1^T + b1)  (bf16)
    k_gemm_mlp1<<<tile_gx, 256, GEMM_SMEM>>>(features, w1, b1, p_xb, M);

    for (int i = 0; i < NL; i++) {
        k_spmm_b<<<warp_blocks, 256>>>(p_rowptr, p_csr_e, p_xb, p_aggb, M);

        const unsigned* wihb = p_wb + OFF_WIH + (size_t)i * 384 * 64;
        const unsigned* whhb = p_wb + OFF_WHH + (size_t)i * 384 * 64;
        const unsigned* g1b  = p_wb + OFF_GW1 + (size_t)i * 128 * 64;
        const unsigned* g2b  = p_wb + OFF_GW2 + (size_t)i * 128 * 64;
        const unsigned* hw1b = p_wb + OFF_HW1 + (size_t)i * 128 * 64;
        const float* bih = gru_bih + (size_t)i * 384;
        const float* bhh = gru_bhh + (size_t)i * 384;

        if (i == 0)
            k_layer<2><<<tile64_gx, 256, LAYER_SMEM>>>(
                p_aggb, p_xb, wihb, whhb, bih, bhh,
                g1b, gin_b1, g2b, gin_b2, hw1b, head_b1, hw2_0, hb2_0,
                out + o_log0, out + o_soft, M);
        else if (i == 1)
            k_layer<6><<<tile64_gx, 256, LAYER_SMEM>>>(
                p_aggb, p_xb, wihb, whhb, bih, bhh,
                g1b, gin_b1 + HDIM, g2b, gin_b2 + HDIM,
                hw1b, head_b1 + HDIM, hw2_1, hb2_1,
                out + o_log1, out + o_soft + (size_t)M * 2, M);
        else
            k_layer<21><<<tile64_gx, 256, LAYER_SMEM>>>(
                p_aggb, p_xb, wihb, whhb, bih, bhh,
                g1b, gin_b1 + 2 * HDIM, g2b, gin_b2 + 2 * HDIM,
                hw1b, head_b1 + 2 * HDIM, hw2_2, hb2_2,
                out + o_log2, out + o_soft + (size_t)M * 8, M);
    }
}